// round 10
// baseline (speedup 1.0000x reference)
#include <cuda_runtime.h>
#include <cuda_fp16.h>

#define N_NODES 100000
#define N_EDGES 1600000
#define IN_DIM  128
#define HID     64
#define N_GRAPHS 64

#define SCAN_B 1024
#define SCAN_NB ((N_NODES + SCAN_B - 1) / SCAN_B)   // 98

// ---------------- static device scratch (no allocations allowed) ----------------
__device__ int   g_cnt[N_NODES];
__device__ int   g_cur[N_NODES];
__device__ int   g_off[N_NODES + 1];
__device__ float g_dis[N_NODES];
__device__ int   g_bsum[SCAN_NB];
__device__ int   g_bpre[SCAN_NB];
__device__ __align__(16) int2   g_csr[N_EDGES];                    // (src, norm-bits)
__device__ __align__(16) __half g_Xh[(size_t)N_NODES * IN_DIM];    // fp16 input features
__device__ __align__(16) __half g_Ah[(size_t)N_NODES * HID];       // GEMM out (messages)
__device__ __align__(16) __half g_Bh[(size_t)N_NODES * HID];       // agg out (layer act)
// weight fragments: [0, K*32) = hi, [K*32, 2*K*32) = lo  (split-fp16)
__device__ __align__(16) unsigned g_Wp1[2 * IN_DIM * 32];
__device__ __align__(16) unsigned g_Wp2[2 * HID * 32];
__device__ __align__(16) unsigned g_Wp3[2 * HID * 32];
__device__ float g_pooled[N_GRAPHS * HID];

// ---------------- preprocessing ----------------
__global__ __launch_bounds__(256) void k_zero() {
    int i = blockIdx.x * blockDim.x + threadIdx.x;
    if (i < N_NODES) { g_cnt[i] = 0; g_cur[i] = 0; }
}

__global__ __launch_bounds__(256) void k_count(const int* __restrict__ dst32) {
    int e = blockIdx.x * blockDim.x + threadIdx.x;
    if (e < N_EDGES) atomicAdd(&g_cnt[dst32[e]], 1);
}

__global__ __launch_bounds__(SCAN_B) void k_scan1() {
    int i = blockIdx.x * SCAN_B + threadIdx.x;
    int v = 0;
    if (i < N_NODES) {
        v = g_cnt[i];
        g_dis[i] = rsqrtf((float)(v + 1));
    }
    int lane = threadIdx.x & 31, wid = threadIdx.x >> 5;
    int s = v;
#pragma unroll
    for (int d = 16; d > 0; d >>= 1) s += __shfl_down_sync(~0u, s, d);
    __shared__ int wsum[32];
    if (lane == 0) wsum[wid] = s;
    __syncthreads();
    if (wid == 0) {
        int t = wsum[lane];
#pragma unroll
        for (int d = 16; d > 0; d >>= 1) t += __shfl_down_sync(~0u, t, d);
        if (lane == 0) g_bsum[blockIdx.x] = t;
    }
}

__global__ __launch_bounds__(128) void k_scan2() {
    __shared__ int sm[128];
    int t = threadIdx.x;
    int v = (t < SCAN_NB) ? g_bsum[t] : 0;
    sm[t] = v;
    __syncthreads();
    for (int d = 1; d < 128; d <<= 1) {
        int y = (t >= d) ? sm[t - d] : 0;
        __syncthreads();
        sm[t] += y;
        __syncthreads();
    }
    if (t < SCAN_NB) g_bpre[t] = sm[t] - v;
    if (t == 0) g_off[N_NODES] = N_EDGES;
}

__global__ __launch_bounds__(SCAN_B) void k_scan3() {
    int i = blockIdx.x * SCAN_B + threadIdx.x;
    int v = (i < N_NODES) ? g_cnt[i] : 0;
    int lane = threadIdx.x & 31, wid = threadIdx.x >> 5;
    int x = v;
#pragma unroll
    for (int d = 1; d < 32; d <<= 1) {
        int y = __shfl_up_sync(~0u, x, d);
        if (lane >= d) x += y;
    }
    __shared__ int wsum[32];
    if (lane == 31) wsum[wid] = x;
    __syncthreads();
    if (wid == 0) {
        int s = wsum[lane];
#pragma unroll
        for (int d = 1; d < 32; d <<= 1) {
            int y = __shfl_up_sync(~0u, s, d);
            if (lane >= d) s += y;
        }
        wsum[lane] = s;
    }
    __syncthreads();
    if (i < N_NODES)
        g_off[i] = (x - v) + (wid > 0 ? wsum[wid - 1] : 0) + g_bpre[blockIdx.x];
}

__global__ __launch_bounds__(256) void k_scatter(const int* __restrict__ ei) {
    int e = blockIdx.x * blockDim.x + threadIdx.x;
    if (e >= N_EDGES) return;
    int s = ei[e];
    int d = ei[N_EDGES + e];
    int pos = g_off[d] + atomicAdd(&g_cur[d], 1);
    float nrm = g_dis[s] * g_dis[d];
    g_csr[pos] = make_int2(s, __float_as_int(nrm));
}

// ---------------- conversions ----------------
__global__ __launch_bounds__(256) void k_xconv(const float* __restrict__ x) {
    int i = blockIdx.x * blockDim.x + threadIdx.x;       // one float4 -> one uint2
    const int total = N_NODES * IN_DIM / 4;
    if (i >= total) return;
    float4 v = ((const float4*)x)[i];
    __half2 h0 = __floats2half2_rn(v.x, v.y);
    __half2 h1 = __floats2half2_rn(v.z, v.w);
    uint2 pk;
    pk.x = *(unsigned*)&h0;
    pk.y = *(unsigned*)&h1;
    ((uint2*)g_Xh)[i] = pk;
}

// W fp32 [K,64] -> split-fp16 B-fragments (m16n8k16 layout)
// idx = ((kt*8+nt)*32 + lane)*2 + r ; lane: t=lane&3, g=lane>>2
// k0 = kt*16 + 2t + 8r ; n = nt*8 + g ; hi at Wp[idx], lo at Wp[K*32 + idx]
__global__ __launch_bounds__(128) void k_wconv(const float* __restrict__ W,
                                               unsigned* __restrict__ Wp, int K) {
    int idx = blockIdx.x * blockDim.x + threadIdx.x;
    if (idx >= K * 32) return;
    int r    = idx & 1;
    int lane = (idx >> 1) & 31;
    int nt   = (idx >> 6) & 7;
    int kt   = idx >> 9;
    int t = lane & 3, g = lane >> 2;
    int k0 = kt * 16 + 2 * t + 8 * r;
    int n  = nt * 8 + g;
    float w0 = W[k0 * 64 + n], w1 = W[(k0 + 1) * 64 + n];
    __half h0 = __float2half_rn(w0), h1 = __float2half_rn(w1);
    __half l0 = __float2half_rn(w0 - __half2float(h0));
    __half l1 = __float2half_rn(w1 - __half2float(h1));
    __half2 hh = __halves2half2(h0, h1);
    __half2 ll = __halves2half2(l0, l1);
    Wp[idx]          = *(unsigned*)&hh;
    Wp[K * 32 + idx] = *(unsigned*)&ll;
}

// ---------------- tensor-core GEMM: g_Ah = act(Xh) @ (W_hi + W_lo) ----------------
// block = 128 thr (4 warps), 128 rows/block: each warp 32 rows (two m16 tiles)
// sharing every B fragment across both tiles -> 2 LDS.64 per 4 MMAs.
template<int K, bool RELU>
__global__ __launch_bounds__(128) void k_gemm_mma(const __half* __restrict__ Xh,
                                                  const unsigned* __restrict__ Wp) {
    __shared__ uint2 Wps[2 * (K / 16) * 8 * 32];
    const uint2* Wp2 = (const uint2*)Wp;
    for (int i = threadIdx.x; i < 2 * (K / 16) * 8 * 32; i += 128) Wps[i] = Wp2[i];
    __syncthreads();

    const int LO = (K / 16) * 8 * 32;    // offset of lo fragments (uint2 units)
    int warp = threadIdx.x >> 5, lane = threadIdx.x & 31;
    int g = lane >> 2, t = lane & 3;
    int base = blockIdx.x * 128 + warp * 32;
    int r0 = base + g;                   // tile0: rows r0, r0+8
    int r1 = base + 16 + g;              // tile1: rows r1, r1+8
    const __half* p0a = Xh + (size_t)min(r0,      N_NODES - 1) * K + 2 * t;
    const __half* p0b = Xh + (size_t)min(r0 + 8,  N_NODES - 1) * K + 2 * t;
    const __half* p1a = Xh + (size_t)min(r1,      N_NODES - 1) * K + 2 * t;
    const __half* p1b = Xh + (size_t)min(r1 + 8,  N_NODES - 1) * K + 2 * t;

    float acc0[8][4], acc1[8][4];
#pragma unroll
    for (int nt = 0; nt < 8; nt++)
#pragma unroll
        for (int j = 0; j < 4; j++) { acc0[nt][j] = 0.0f; acc1[nt][j] = 0.0f; }

    const __half2 zero2 = __float2half2_rn(0.0f);
#pragma unroll
    for (int kt = 0; kt < K / 16; kt++) {
        unsigned a0 = *(const unsigned*)(p0a + kt * 16);
        unsigned a1 = *(const unsigned*)(p0b + kt * 16);
        unsigned a2 = *(const unsigned*)(p0a + kt * 16 + 8);
        unsigned a3 = *(const unsigned*)(p0b + kt * 16 + 8);
        unsigned c0 = *(const unsigned*)(p1a + kt * 16);
        unsigned c1 = *(const unsigned*)(p1b + kt * 16);
        unsigned c2 = *(const unsigned*)(p1a + kt * 16 + 8);
        unsigned c3 = *(const unsigned*)(p1b + kt * 16 + 8);
        if (RELU) {
            __half2 v;
            v = __hmax2(*(__half2*)&a0, zero2); a0 = *(unsigned*)&v;
            v = __hmax2(*(__half2*)&a1, zero2); a1 = *(unsigned*)&v;
            v = __hmax2(*(__half2*)&a2, zero2); a2 = *(unsigned*)&v;
            v = __hmax2(*(__half2*)&a3, zero2); a3 = *(unsigned*)&v;
            v = __hmax2(*(__half2*)&c0, zero2); c0 = *(unsigned*)&v;
            v = __hmax2(*(__half2*)&c1, zero2); c1 = *(unsigned*)&v;
            v = __hmax2(*(__half2*)&c2, zero2); c2 = *(unsigned*)&v;
            v = __hmax2(*(__half2*)&c3, zero2); c3 = *(unsigned*)&v;
        }
#pragma unroll
        for (int nt = 0; nt < 8; nt++) {
            uint2 bh = Wps[(kt * 8 + nt) * 32 + lane];
            uint2 bl = Wps[LO + (kt * 8 + nt) * 32 + lane];
            asm volatile(
                "mma.sync.aligned.m16n8k16.row.col.f32.f16.f16.f32 "
                "{%0,%1,%2,%3}, {%4,%5,%6,%7}, {%8,%9}, {%0,%1,%2,%3};"
                : "+f"(acc0[nt][0]), "+f"(acc0[nt][1]), "+f"(acc0[nt][2]), "+f"(acc0[nt][3])
                : "r"(a0), "r"(a1), "r"(a2), "r"(a3), "r"(bh.x), "r"(bh.y));
            asm volatile(
                "mma.sync.aligned.m16n8k16.row.col.f32.f16.f16.f32 "
                "{%0,%1,%2,%3}, {%4,%5,%6,%7}, {%8,%9}, {%0,%1,%2,%3};"
                : "+f"(acc0[nt][0]), "+f"(acc0[nt][1]), "+f"(acc0[nt][2]), "+f"(acc0[nt][3])
                : "r"(a0), "r"(a1), "r"(a2), "r"(a3), "r"(bl.x), "r"(bl.y));
            asm volatile(
                "mma.sync.aligned.m16n8k16.row.col.f32.f16.f16.f32 "
                "{%0,%1,%2,%3}, {%4,%5,%6,%7}, {%8,%9}, {%0,%1,%2,%3};"
                : "+f"(acc1[nt][0]), "+f"(acc1[nt][1]), "+f"(acc1[nt][2]), "+f"(acc1[nt][3])
                : "r"(c0), "r"(c1), "r"(c2), "r"(c3), "r"(bh.x), "r"(bh.y));
            asm volatile(
                "mma.sync.aligned.m16n8k16.row.col.f32.f16.f16.f32 "
                "{%0,%1,%2,%3}, {%4,%5,%6,%7}, {%8,%9}, {%0,%1,%2,%3};"
                : "+f"(acc1[nt][0]), "+f"(acc1[nt][1]), "+f"(acc1[nt][2]), "+f"(acc1[nt][3])
                : "r"(c0), "r"(c1), "r"(c2), "r"(c3), "r"(bl.x), "r"(bl.y));
        }
    }

#pragma unroll
    for (int tile = 0; tile < 2; tile++) {
        float (*acc)[4] = tile ? acc1 : acc0;
        int ra = (tile ? r1 : r0);
        if (ra < N_NODES) {
#pragma unroll
            for (int nt = 0; nt < 8; nt++) {
                __half2 h = __floats2half2_rn(acc[nt][0], acc[nt][1]);
                *(unsigned*)&g_Ah[(size_t)ra * HID + nt * 8 + 2 * t] = *(unsigned*)&h;
            }
        }
        if (ra + 8 < N_NODES) {
#pragma unroll
            for (int nt = 0; nt < 8; nt++) {
                __half2 h = __floats2half2_rn(acc[nt][2], acc[nt][3]);
                *(unsigned*)&g_Ah[(size_t)(ra + 8) * HID + nt * 8 + 2 * t] = *(unsigned*)&h;
            }
        }
    }
}

// ---------------- aggregation: one warp per dst node (2-edge unroll) ----------------
__global__ __launch_bounds__(256) void k_agg(const float* __restrict__ bias) {
    int w = (blockIdx.x * blockDim.x + threadIdx.x) >> 5;
    if (w >= N_NODES) return;
    int lane = threadIdx.x & 31;

    const __half2* A2 = (const __half2*)g_Ah;
    float dis = g_dis[w];
    float2 b2 = ((const float2*)bias)[lane];
    float2 self = __half22float2(A2[(size_t)w * 32 + lane]);
    float sn = dis * dis;
    float ax = self.x * sn + b2.x;
    float ay = self.y * sn + b2.y;

    int p   = g_off[w];
    int end = g_off[w + 1];
    for (; p + 2 <= end; p += 2) {
        int2 e0 = g_csr[p];
        int2 e1 = g_csr[p + 1];
        float n0 = __int_as_float(e0.y);
        float n1 = __int_as_float(e1.y);
        float2 v0 = __half22float2(A2[(size_t)e0.x * 32 + lane]);
        float2 v1 = __half22float2(A2[(size_t)e1.x * 32 + lane]);
        ax += v0.x * n0; ay += v0.y * n0;
        ax += v1.x * n1; ay += v1.y * n1;
    }
    if (p < end) {
        int2 e0 = g_csr[p];
        float n0 = __int_as_float(e0.y);
        float2 v0 = __half22float2(A2[(size_t)e0.x * 32 + lane]);
        ax += v0.x * n0; ay += v0.y * n0;
    }

    ((__half2*)g_Bh)[(size_t)w * 32 + lane] = __floats2half2_rn(ax, ay);
}

// ---------------- global mean pool (batch is sorted int32) ----------------
__device__ __forceinline__ int lb_i32(const int* a, int n, int v) {
    int lo = 0, hi = n;
    while (lo < hi) {
        int mid = (lo + hi) >> 1;
        if (a[mid] < v) lo = mid + 1; else hi = mid;
    }
    return lo;
}

__global__ __launch_bounds__(256) void k_pool(const int* __restrict__ batch) {
    int g = blockIdx.x;
    int lo = lb_i32(batch, N_NODES, g);
    int hi = lb_i32(batch, N_NODES, g + 1);
    int c2 = threadIdx.x & 31;          // half2 column (2 cols per thread)
    int sub = threadIdx.x >> 5;         // 0..7
    const __half2* B2 = (const __half2*)g_Bh;
    float sx = 0.0f, sy = 0.0f;
    for (int i = lo + sub; i < hi; i += 8) {
        float2 v = __half22float2(B2[(size_t)i * 32 + c2]);
        sx += v.x; sy += v.y;
    }
    __shared__ float redx[256], redy[256];
    redx[threadIdx.x] = sx;
    redy[threadIdx.x] = sy;
    __syncthreads();
    if (sub == 0) {
        float tx = 0.0f, ty = 0.0f;
#pragma unroll
        for (int q = 0; q < 8; q++) { tx += redx[q * 32 + c2]; ty += redy[q * 32 + c2]; }
        float inv = 1.0f / fmaxf((float)(hi - lo), 1.0f);
        g_pooled[g * HID + 2 * c2]     = tx * inv;
        g_pooled[g * HID + 2 * c2 + 1] = ty * inv;
    }
}

// ---------------- classifier MLP ----------------
__global__ __launch_bounds__(64) void k_cls(const float* __restrict__ Wc1,
                                            const float* __restrict__ bc1,
                                            const float* __restrict__ Wc2,
                                            const float* __restrict__ bc2,
                                            float* __restrict__ out) {
    __shared__ float W1s[64 * 32];
    __shared__ float W2s[32 * 2];
    int t = threadIdx.x;
    for (int i = t; i < 64 * 32; i += 64) W1s[i] = Wc1[i];
    if (t < 64) W2s[t] = Wc2[t];
    __syncthreads();

    float p[64];
#pragma unroll
    for (int k = 0; k < 64; k++) p[k] = g_pooled[t * 64 + k];

    float h[32];
#pragma unroll
    for (int j = 0; j < 32; j++) {
        float s = bc1[j];
#pragma unroll
        for (int k = 0; k < 64; k++) s += p[k] * W1s[k * 32 + j];
        h[j] = fmaxf(s, 0.0f);
    }
#pragma unroll
    for (int o = 0; o < 2; o++) {
        float s = bc2[o];
#pragma unroll
        for (int j = 0; j < 32; j++) s += h[j] * W2s[j * 2 + o];
        out[t * 2 + o] = s;
    }
}

// ---------------- launch ----------------
extern "C" void kernel_launch(void* const* d_in, const int* in_sizes, int n_in,
                              void* d_out, int out_size) {
    const float* x     = (const float*)d_in[0];
    const int*   ei    = (const int*)d_in[1];
    const int*   batch = (const int*)d_in[2];
    const float* W1  = (const float*)d_in[3];
    const float* b1  = (const float*)d_in[4];
    const float* W2  = (const float*)d_in[5];
    const float* b2  = (const float*)d_in[6];
    const float* W3  = (const float*)d_in[7];
    const float* b3  = (const float*)d_in[8];
    const float* Wc1 = (const float*)d_in[9];
    const float* bc1 = (const float*)d_in[10];
    const float* Wc2 = (const float*)d_in[11];
    const float* bc2 = (const float*)d_in[12];
    float* out = (float*)d_out;

    const int TB = 256;
    const int gN  = (N_NODES + TB - 1) / TB;
    const int gE  = (N_EDGES + TB - 1) / TB;
    const int gW  = (N_NODES * 32 + TB - 1) / TB;
    const int gM  = (N_NODES + 127) / 128;                   // mma gemm grid (128 rows/blk)
    const int gX  = (N_NODES * IN_DIM / 4 + TB - 1) / TB;

    // DEVICE addresses of __device__ globals (host symbol is NOT the device ptr!)
    unsigned *wp1, *wp2, *wp3;
    __half *xh, *bh;
    cudaGetSymbolAddress((void**)&wp1, g_Wp1);
    cudaGetSymbolAddress((void**)&wp2, g_Wp2);
    cudaGetSymbolAddress((void**)&wp3, g_Wp3);
    cudaGetSymbolAddress((void**)&xh,  g_Xh);
    cudaGetSymbolAddress((void**)&bh,  g_Bh);

    // conversions
    k_xconv<<<gX, TB>>>(x);
    k_wconv<<<(IN_DIM * 32 + 127) / 128, 128>>>(W1, wp1, IN_DIM);
    k_wconv<<<(HID * 32 + 127) / 128, 128>>>(W2, wp2, HID);
    k_wconv<<<(HID * 32 + 127) / 128, 128>>>(W3, wp3, HID);

    // CSR-by-dst preprocessing
    k_zero<<<gN, TB>>>();
    k_count<<<gE, TB>>>(ei + N_EDGES);
    k_scan1<<<SCAN_NB, SCAN_B>>>();
    k_scan2<<<1, 128>>>();
    k_scan3<<<SCAN_NB, SCAN_B>>>();
    k_scatter<<<gE, TB>>>(ei);

    // layer 1
    k_gemm_mma<IN_DIM, false><<<gM, 128>>>(xh, wp1);
    k_agg<<<gW, TB>>>(b1);
    // layer 2
    k_gemm_mma<HID, true><<<gM, 128>>>(bh, wp2);
    k_agg<<<gW, TB>>>(b2);
    // layer 3
    k_gemm_mma<HID, true><<<gM, 128>>>(bh, wp3);
    k_agg<<<gW, TB>>>(b3);

    // pool + classifier
    k_pool<<<N_GRAPHS, 256>>>(batch);
    k_cls<<<1, 64>>>(Wc1, bc1, Wc2, bc2, out);
}

// round 11
// speedup vs baseline: 1.4473x; 1.4473x over previous
#include <cuda_runtime.h>
#include <cuda_fp16.h>

#define N_NODES 100000
#define N_EDGES 1600000
#define IN_DIM  128
#define HID     64
#define N_GRAPHS 64

#define SCAN_B 1024
#define SCAN_NB ((N_NODES + SCAN_B - 1) / SCAN_B)   // 98

// ---------------- static device scratch (no allocations allowed) ----------------
__device__ int   g_cnt[N_NODES];
__device__ int   g_cur[N_NODES];
__device__ int   g_off[N_NODES + 1];
__device__ float g_dis[N_NODES];
__device__ int   g_bsum[SCAN_NB];
__device__ int   g_bpre[SCAN_NB];
__device__ __align__(16) int2   g_csr[N_EDGES];                    // (src, norm-bits)
__device__ __align__(16) __half g_Xh[(size_t)N_NODES * IN_DIM];    // fp16 input features
__device__ __align__(16) __half g_Ah[(size_t)N_NODES * HID];       // GEMM out (messages)
__device__ __align__(16) __half g_Bh[(size_t)N_NODES * HID];       // agg out (layer act)
// interleaved split-fp16 weight fragments: one uint4 = {hi0, hi1, lo0, lo1} per (frag,lane)
__device__ __align__(16) uint4 g_Wp1[IN_DIM * 16];   // (K/16)*8*32 = K*16 uint4
__device__ __align__(16) uint4 g_Wp2[HID * 16];
__device__ __align__(16) uint4 g_Wp3[HID * 16];
__device__ float g_pooled[N_GRAPHS * HID];

// ---------------- preprocessing ----------------
__global__ __launch_bounds__(256) void k_zero() {
    int i = blockIdx.x * blockDim.x + threadIdx.x;
    if (i < N_NODES) { g_cnt[i] = 0; g_cur[i] = 0; }
}

__global__ __launch_bounds__(256) void k_count(const int* __restrict__ dst32) {
    int e = blockIdx.x * blockDim.x + threadIdx.x;
    if (e < N_EDGES) atomicAdd(&g_cnt[dst32[e]], 1);
}

__global__ __launch_bounds__(SCAN_B) void k_scan1() {
    int i = blockIdx.x * SCAN_B + threadIdx.x;
    int v = 0;
    if (i < N_NODES) {
        v = g_cnt[i];
        g_dis[i] = rsqrtf((float)(v + 1));
    }
    int lane = threadIdx.x & 31, wid = threadIdx.x >> 5;
    int s = v;
#pragma unroll
    for (int d = 16; d > 0; d >>= 1) s += __shfl_down_sync(~0u, s, d);
    __shared__ int wsum[32];
    if (lane == 0) wsum[wid] = s;
    __syncthreads();
    if (wid == 0) {
        int t = wsum[lane];
#pragma unroll
        for (int d = 16; d > 0; d >>= 1) t += __shfl_down_sync(~0u, t, d);
        if (lane == 0) g_bsum[blockIdx.x] = t;
    }
}

__global__ __launch_bounds__(128) void k_scan2() {
    __shared__ int sm[128];
    int t = threadIdx.x;
    int v = (t < SCAN_NB) ? g_bsum[t] : 0;
    sm[t] = v;
    __syncthreads();
    for (int d = 1; d < 128; d <<= 1) {
        int y = (t >= d) ? sm[t - d] : 0;
        __syncthreads();
        sm[t] += y;
        __syncthreads();
    }
    if (t < SCAN_NB) g_bpre[t] = sm[t] - v;
    if (t == 0) g_off[N_NODES] = N_EDGES;
}

__global__ __launch_bounds__(SCAN_B) void k_scan3() {
    int i = blockIdx.x * SCAN_B + threadIdx.x;
    int v = (i < N_NODES) ? g_cnt[i] : 0;
    int lane = threadIdx.x & 31, wid = threadIdx.x >> 5;
    int x = v;
#pragma unroll
    for (int d = 1; d < 32; d <<= 1) {
        int y = __shfl_up_sync(~0u, x, d);
        if (lane >= d) x += y;
    }
    __shared__ int wsum[32];
    if (lane == 31) wsum[wid] = x;
    __syncthreads();
    if (wid == 0) {
        int s = wsum[lane];
#pragma unroll
        for (int d = 1; d < 32; d <<= 1) {
            int y = __shfl_up_sync(~0u, s, d);
            if (lane >= d) s += y;
        }
        wsum[lane] = s;
    }
    __syncthreads();
    if (i < N_NODES)
        g_off[i] = (x - v) + (wid > 0 ? wsum[wid - 1] : 0) + g_bpre[blockIdx.x];
}

__global__ __launch_bounds__(256) void k_scatter(const int* __restrict__ ei) {
    int e = blockIdx.x * blockDim.x + threadIdx.x;
    if (e >= N_EDGES) return;
    int s = ei[e];
    int d = ei[N_EDGES + e];
    int pos = g_off[d] + atomicAdd(&g_cur[d], 1);
    float nrm = g_dis[s] * g_dis[d];
    g_csr[pos] = make_int2(s, __float_as_int(nrm));
}

// ---------------- conversions ----------------
__global__ __launch_bounds__(256) void k_xconv(const float* __restrict__ x) {
    int i = blockIdx.x * blockDim.x + threadIdx.x;       // one float4 -> one uint2
    const int total = N_NODES * IN_DIM / 4;
    if (i >= total) return;
    float4 v = ((const float4*)x)[i];
    __half2 h0 = __floats2half2_rn(v.x, v.y);
    __half2 h1 = __floats2half2_rn(v.z, v.w);
    uint2 pk;
    pk.x = *(unsigned*)&h0;
    pk.y = *(unsigned*)&h1;
    ((uint2*)g_Xh)[i] = pk;
}

// W fp32 [K,64] -> interleaved split-fp16 B-fragments (m16n8k16 layout)
// one thread per (frag, lane): idx over (K/16)*8*32 = K*16
//   lane: t=lane&3, g=lane>>2 ; n = nt*8+g ; r in {0,1}: k0 = kt*16 + 2t + 8r
//   out uint4 = { hi_r0, hi_r1, lo_r0, lo_r1 }
__global__ __launch_bounds__(128) void k_wconv(const float* __restrict__ W,
                                               uint4* __restrict__ Wp, int K) {
    int idx = blockIdx.x * blockDim.x + threadIdx.x;
    if (idx >= K * 16) return;
    int lane = idx & 31;
    int nt   = (idx >> 5) & 7;
    int kt   = idx >> 8;
    int t = lane & 3, g = lane >> 2;
    int n = nt * 8 + g;
    unsigned hi[2], lo[2];
#pragma unroll
    for (int r = 0; r < 2; r++) {
        int k0 = kt * 16 + 2 * t + 8 * r;
        float w0 = W[k0 * 64 + n], w1 = W[(k0 + 1) * 64 + n];
        __half h0 = __float2half_rn(w0), h1 = __float2half_rn(w1);
        __half l0 = __float2half_rn(w0 - __half2float(h0));
        __half l1 = __float2half_rn(w1 - __half2float(h1));
        __half2 hh = __halves2half2(h0, h1);
        __half2 ll = __halves2half2(l0, l1);
        hi[r] = *(unsigned*)&hh;
        lo[r] = *(unsigned*)&ll;
    }
    Wp[idx] = make_uint4(hi[0], hi[1], lo[0], lo[1]);
}

// ---------------- tensor-core GEMM: g_Ah = act(Xh) @ (W_hi + W_lo) ----------------
// block = 128 thr (4 warps), 64 rows/block, each warp 16 rows x 64 cols.
// One LDS.128 per (kt,nt) feeds both hi and lo MMAs.
template<int K, bool RELU>
__global__ __launch_bounds__(128) void k_gemm_mma(const __half* __restrict__ Xh,
                                                  const uint4* __restrict__ Wp) {
    __shared__ uint4 Wps[(K / 16) * 8 * 32];
    for (int i = threadIdx.x; i < (K / 16) * 8 * 32; i += 128) Wps[i] = Wp[i];
    __syncthreads();

    int warp = threadIdx.x >> 5, lane = threadIdx.x & 31;
    int g = lane >> 2, t = lane & 3;
    int row0 = blockIdx.x * 64 + warp * 16 + g;          // rows row0 and row0+8
    long rA = min(row0, N_NODES - 1);
    long rB = min(row0 + 8, N_NODES - 1);
    const __half* pa = Xh + rA * K + 2 * t;
    const __half* pb = Xh + rB * K + 2 * t;

    float acc[8][4];
#pragma unroll
    for (int nt = 0; nt < 8; nt++)
#pragma unroll
        for (int j = 0; j < 4; j++) acc[nt][j] = 0.0f;

    const __half2 zero2 = __float2half2_rn(0.0f);
#pragma unroll
    for (int kt = 0; kt < K / 16; kt++) {
        unsigned a0 = *(const unsigned*)(pa + kt * 16);
        unsigned a1 = *(const unsigned*)(pb + kt * 16);
        unsigned a2 = *(const unsigned*)(pa + kt * 16 + 8);
        unsigned a3 = *(const unsigned*)(pb + kt * 16 + 8);
        if (RELU) {
            __half2 v;
            v = __hmax2(*(__half2*)&a0, zero2); a0 = *(unsigned*)&v;
            v = __hmax2(*(__half2*)&a1, zero2); a1 = *(unsigned*)&v;
            v = __hmax2(*(__half2*)&a2, zero2); a2 = *(unsigned*)&v;
            v = __hmax2(*(__half2*)&a3, zero2); a3 = *(unsigned*)&v;
        }
#pragma unroll
        for (int nt = 0; nt < 8; nt++) {
            uint4 b = Wps[(kt * 8 + nt) * 32 + lane];    // {hi0,hi1,lo0,lo1}
            asm volatile(
                "mma.sync.aligned.m16n8k16.row.col.f32.f16.f16.f32 "
                "{%0,%1,%2,%3}, {%4,%5,%6,%7}, {%8,%9}, {%0,%1,%2,%3};"
                : "+f"(acc[nt][0]), "+f"(acc[nt][1]), "+f"(acc[nt][2]), "+f"(acc[nt][3])
                : "r"(a0), "r"(a1), "r"(a2), "r"(a3), "r"(b.x), "r"(b.y));
            asm volatile(
                "mma.sync.aligned.m16n8k16.row.col.f32.f16.f16.f32 "
                "{%0,%1,%2,%3}, {%4,%5,%6,%7}, {%8,%9}, {%0,%1,%2,%3};"
                : "+f"(acc[nt][0]), "+f"(acc[nt][1]), "+f"(acc[nt][2]), "+f"(acc[nt][3])
                : "r"(a0), "r"(a1), "r"(a2), "r"(a3), "r"(b.z), "r"(b.w));
        }
    }

    if (row0 < N_NODES) {
#pragma unroll
        for (int nt = 0; nt < 8; nt++) {
            __half2 h = __floats2half2_rn(acc[nt][0], acc[nt][1]);
            *(unsigned*)&g_Ah[(size_t)row0 * HID + nt * 8 + 2 * t] = *(unsigned*)&h;
        }
    }
    if (row0 + 8 < N_NODES) {
#pragma unroll
        for (int nt = 0; nt < 8; nt++) {
            __half2 h = __floats2half2_rn(acc[nt][2], acc[nt][3]);
            *(unsigned*)&g_Ah[(size_t)(row0 + 8) * HID + nt * 8 + 2 * t] = *(unsigned*)&h;
        }
    }
}

// ---------------- aggregation: one warp per dst node (2-edge unroll) ----------------
__global__ __launch_bounds__(256) void k_agg(const float* __restrict__ bias) {
    int w = (blockIdx.x * blockDim.x + threadIdx.x) >> 5;
    if (w >= N_NODES) return;
    int lane = threadIdx.x & 31;

    const __half2* A2 = (const __half2*)g_Ah;
    float dis = g_dis[w];
    float2 b2 = ((const float2*)bias)[lane];
    float2 self = __half22float2(A2[(size_t)w * 32 + lane]);
    float sn = dis * dis;
    float ax = self.x * sn + b2.x;
    float ay = self.y * sn + b2.y;

    int p   = g_off[w];
    int end = g_off[w + 1];
    for (; p + 2 <= end; p += 2) {
        int2 e0 = g_csr[p];
        int2 e1 = g_csr[p + 1];
        float n0 = __int_as_float(e0.y);
        float n1 = __int_as_float(e1.y);
        float2 v0 = __half22float2(A2[(size_t)e0.x * 32 + lane]);
        float2 v1 = __half22float2(A2[(size_t)e1.x * 32 + lane]);
        ax += v0.x * n0; ay += v0.y * n0;
        ax += v1.x * n1; ay += v1.y * n1;
    }
    if (p < end) {
        int2 e0 = g_csr[p];
        float n0 = __int_as_float(e0.y);
        float2 v0 = __half22float2(A2[(size_t)e0.x * 32 + lane]);
        ax += v0.x * n0; ay += v0.y * n0;
    }

    ((__half2*)g_Bh)[(size_t)w * 32 + lane] = __floats2half2_rn(ax, ay);
}

// ---------------- global mean pool (batch is sorted int32) ----------------
__device__ __forceinline__ int lb_i32(const int* a, int n, int v) {
    int lo = 0, hi = n;
    while (lo < hi) {
        int mid = (lo + hi) >> 1;
        if (a[mid] < v) lo = mid + 1; else hi = mid;
    }
    return lo;
}

__global__ __launch_bounds__(256) void k_pool(const int* __restrict__ batch) {
    int g = blockIdx.x;
    int lo = lb_i32(batch, N_NODES, g);
    int hi = lb_i32(batch, N_NODES, g + 1);
    int c2 = threadIdx.x & 31;          // half2 column (2 cols per thread)
    int sub = threadIdx.x >> 5;         // 0..7
    const __half2* B2 = (const __half2*)g_Bh;
    float sx = 0.0f, sy = 0.0f;
    for (int i = lo + sub; i < hi; i += 8) {
        float2 v = __half22float2(B2[(size_t)i * 32 + c2]);
        sx += v.x; sy += v.y;
    }
    __shared__ float redx[256], redy[256];
    redx[threadIdx.x] = sx;
    redy[threadIdx.x] = sy;
    __syncthreads();
    if (sub == 0) {
        float tx = 0.0f, ty = 0.0f;
#pragma unroll
        for (int q = 0; q < 8; q++) { tx += redx[q * 32 + c2]; ty += redy[q * 32 + c2]; }
        float inv = 1.0f / fmaxf((float)(hi - lo), 1.0f);
        g_pooled[g * HID + 2 * c2]     = tx * inv;
        g_pooled[g * HID + 2 * c2 + 1] = ty * inv;
    }
}

// ---------------- classifier MLP ----------------
__global__ __launch_bounds__(64) void k_cls(const float* __restrict__ Wc1,
                                            const float* __restrict__ bc1,
                                            const float* __restrict__ Wc2,
                                            const float* __restrict__ bc2,
                                            float* __restrict__ out) {
    __shared__ float W1s[64 * 32];
    __shared__ float W2s[32 * 2];
    int t = threadIdx.x;
    for (int i = t; i < 64 * 32; i += 64) W1s[i] = Wc1[i];
    if (t < 64) W2s[t] = Wc2[t];
    __syncthreads();

    float p[64];
#pragma unroll
    for (int k = 0; k < 64; k++) p[k] = g_pooled[t * 64 + k];

    float h[32];
#pragma unroll
    for (int j = 0; j < 32; j++) {
        float s = bc1[j];
#pragma unroll
        for (int k = 0; k < 64; k++) s += p[k] * W1s[k * 32 + j];
        h[j] = fmaxf(s, 0.0f);
    }
#pragma unroll
    for (int o = 0; o < 2; o++) {
        float s = bc2[o];
#pragma unroll
        for (int j = 0; j < 32; j++) s += h[j] * W2s[j * 2 + o];
        out[t * 2 + o] = s;
    }
}

// ---------------- launch ----------------
extern "C" void kernel_launch(void* const* d_in, const int* in_sizes, int n_in,
                              void* d_out, int out_size) {
    const float* x     = (const float*)d_in[0];
    const int*   ei    = (const int*)d_in[1];
    const int*   batch = (const int*)d_in[2];
    const float* W1  = (const float*)d_in[3];
    const float* b1  = (const float*)d_in[4];
    const float* W2  = (const float*)d_in[5];
    const float* b2  = (const float*)d_in[6];
    const float* W3  = (const float*)d_in[7];
    const float* b3  = (const float*)d_in[8];
    const float* Wc1 = (const float*)d_in[9];
    const float* bc1 = (const float*)d_in[10];
    const float* Wc2 = (const float*)d_in[11];
    const float* bc2 = (const float*)d_in[12];
    float* out = (float*)d_out;

    const int TB = 256;
    const int gN  = (N_NODES + TB - 1) / TB;
    const int gE  = (N_EDGES + TB - 1) / TB;
    const int gW  = (N_NODES * 32 + TB - 1) / TB;
    const int gM  = (N_NODES + 63) / 64;                     // mma gemm grid (64 rows/blk)
    const int gX  = (N_NODES * IN_DIM / 4 + TB - 1) / TB;

    // DEVICE addresses of __device__ globals (host symbol is NOT the device ptr!)
    uint4 *wp1, *wp2, *wp3;
    __half *xh, *bh;
    cudaGetSymbolAddress((void**)&wp1, g_Wp1);
    cudaGetSymbolAddress((void**)&wp2, g_Wp2);
    cudaGetSymbolAddress((void**)&wp3, g_Wp3);
    cudaGetSymbolAddress((void**)&xh,  g_Xh);
    cudaGetSymbolAddress((void**)&bh,  g_Bh);

    // conversions
    k_xconv<<<gX, TB>>>(x);
    k_wconv<<<(IN_DIM * 16 + 127) / 128, 128>>>(W1, wp1, IN_DIM);
    k_wconv<<<(HID * 16 + 127) / 128, 128>>>(W2, wp2, HID);
    k_wconv<<<(HID * 16 + 127) / 128, 128>>>(W3, wp3, HID);

    // CSR-by-dst preprocessing
    k_zero<<<gN, TB>>>();
    k_count<<<gE, TB>>>(ei + N_EDGES);
    k_scan1<<<SCAN_NB, SCAN_B>>>();
    k_scan2<<<1, 128>>>();
    k_scan3<<<SCAN_NB, SCAN_B>>>();
    k_scatter<<<gE, TB>>>(ei);

    // layer 1
    k_gemm_mma<IN_DIM, false><<<gM, 128>>>(xh, wp1);
    k_agg<<<gW, TB>>>(b1);
    // layer 2
    k_gemm_mma<HID, true><<<gM, 128>>>(bh, wp2);
    k_agg<<<gW, TB>>>(b2);
    // layer 3
    k_gemm_mma<HID, true><<<gM, 128>>>(bh, wp3);
    k_agg<<<gW, TB>>>(b3);

    // pool + classifier
    k_pool<<<N_GRAPHS, 256>>>(batch);
    k_cls<<<1, 64>>>(Wc1, bc1, Wc2, bc2, out);
}

// round 12
// speedup vs baseline: 1.5308x; 1.0577x over previous
#include <cuda_runtime.h>
#include <cuda_fp16.h>

#define N_NODES 100000
#define N_EDGES 1600000
#define IN_DIM  128
#define HID     64
#define N_GRAPHS 64

#define SCAN_B 1024
#define SCAN_NB ((N_NODES + SCAN_B - 1) / SCAN_B)   // 98

// ---------------- static device scratch (no allocations allowed) ----------------
__device__ int   g_cnt[N_NODES];
__device__ int   g_cur[N_NODES];
__device__ int   g_off[N_NODES + 1];
__device__ float g_dis[N_NODES];
__device__ int   g_bsum[SCAN_NB];
__device__ int   g_bpre[SCAN_NB];
__device__ __align__(16) int2   g_csr[N_EDGES];                    // (src, norm-bits)
__device__ __align__(16) __half g_Xh[(size_t)N_NODES * IN_DIM];    // fp16 input features
__device__ __align__(16) __half g_Ah[(size_t)N_NODES * HID];       // GEMM out (messages)
__device__ __align__(16) __half g_Bh[(size_t)N_NODES * HID];       // agg out (layer act)
// interleaved split-fp16 weight fragments: one uint4 = {hi0, hi1, lo0, lo1} per (frag,lane)
__device__ __align__(16) uint4 g_Wp1[IN_DIM * 16];   // (K/16)*8*32 = K*16 uint4
__device__ __align__(16) uint4 g_Wp2[HID * 16];
__device__ __align__(16) uint4 g_Wp3[HID * 16];
__device__ float g_pooled[N_GRAPHS * HID];

// ---------------- preprocessing ----------------
__global__ __launch_bounds__(256) void k_zero() {
    int i = blockIdx.x * blockDim.x + threadIdx.x;
    if (i < N_NODES) { g_cnt[i] = 0; g_cur[i] = 0; }
}

__global__ __launch_bounds__(256) void k_count(const int* __restrict__ dst32) {
    int e = blockIdx.x * blockDim.x + threadIdx.x;
    if (e < N_EDGES) atomicAdd(&g_cnt[dst32[e]], 1);
}

__global__ __launch_bounds__(SCAN_B) void k_scan1() {
    int i = blockIdx.x * SCAN_B + threadIdx.x;
    int v = 0;
    if (i < N_NODES) {
        v = g_cnt[i];
        g_dis[i] = rsqrtf((float)(v + 1));
    }
    int lane = threadIdx.x & 31, wid = threadIdx.x >> 5;
    int s = v;
#pragma unroll
    for (int d = 16; d > 0; d >>= 1) s += __shfl_down_sync(~0u, s, d);
    __shared__ int wsum[32];
    if (lane == 0) wsum[wid] = s;
    __syncthreads();
    if (wid == 0) {
        int t = wsum[lane];
#pragma unroll
        for (int d = 16; d > 0; d >>= 1) t += __shfl_down_sync(~0u, t, d);
        if (lane == 0) g_bsum[blockIdx.x] = t;
    }
}

__global__ __launch_bounds__(128) void k_scan2() {
    __shared__ int sm[128];
    int t = threadIdx.x;
    int v = (t < SCAN_NB) ? g_bsum[t] : 0;
    sm[t] = v;
    __syncthreads();
    for (int d = 1; d < 128; d <<= 1) {
        int y = (t >= d) ? sm[t - d] : 0;
        __syncthreads();
        sm[t] += y;
        __syncthreads();
    }
    if (t < SCAN_NB) g_bpre[t] = sm[t] - v;
    if (t == 0) g_off[N_NODES] = N_EDGES;
}

__global__ __launch_bounds__(SCAN_B) void k_scan3() {
    int i = blockIdx.x * SCAN_B + threadIdx.x;
    int v = (i < N_NODES) ? g_cnt[i] : 0;
    int lane = threadIdx.x & 31, wid = threadIdx.x >> 5;
    int x = v;
#pragma unroll
    for (int d = 1; d < 32; d <<= 1) {
        int y = __shfl_up_sync(~0u, x, d);
        if (lane >= d) x += y;
    }
    __shared__ int wsum[32];
    if (lane == 31) wsum[wid] = x;
    __syncthreads();
    if (wid == 0) {
        int s = wsum[lane];
#pragma unroll
        for (int d = 1; d < 32; d <<= 1) {
            int y = __shfl_up_sync(~0u, s, d);
            if (lane >= d) s += y;
        }
        wsum[lane] = s;
    }
    __syncthreads();
    if (i < N_NODES)
        g_off[i] = (x - v) + (wid > 0 ? wsum[wid - 1] : 0) + g_bpre[blockIdx.x];
}

__global__ __launch_bounds__(256) void k_scatter(const int* __restrict__ ei) {
    int e = blockIdx.x * blockDim.x + threadIdx.x;
    if (e >= N_EDGES) return;
    int s = ei[e];
    int d = ei[N_EDGES + e];
    int pos = g_off[d] + atomicAdd(&g_cur[d], 1);
    float nrm = g_dis[s] * g_dis[d];
    g_csr[pos] = make_int2(s, __float_as_int(nrm));
}

// ---------------- conversions ----------------
__global__ __launch_bounds__(256) void k_xconv(const float* __restrict__ x) {
    int i = blockIdx.x * blockDim.x + threadIdx.x;       // one float4 -> one uint2
    const int total = N_NODES * IN_DIM / 4;
    if (i >= total) return;
    float4 v = ((const float4*)x)[i];
    __half2 h0 = __floats2half2_rn(v.x, v.y);
    __half2 h1 = __floats2half2_rn(v.z, v.w);
    uint2 pk;
    pk.x = *(unsigned*)&h0;
    pk.y = *(unsigned*)&h1;
    ((uint2*)g_Xh)[i] = pk;
}

// W fp32 [K,64] -> interleaved split-fp16 B-fragments (m16n8k16 layout)
__global__ __launch_bounds__(128) void k_wconv(const float* __restrict__ W,
                                               uint4* __restrict__ Wp, int K) {
    int idx = blockIdx.x * blockDim.x + threadIdx.x;
    if (idx >= K * 16) return;
    int lane = idx & 31;
    int nt   = (idx >> 5) & 7;
    int kt   = idx >> 8;
    int t = lane & 3, g = lane >> 2;
    int n = nt * 8 + g;
    unsigned hi[2], lo[2];
#pragma unroll
    for (int r = 0; r < 2; r++) {
        int k0 = kt * 16 + 2 * t + 8 * r;
        float w0 = W[k0 * 64 + n], w1 = W[(k0 + 1) * 64 + n];
        __half h0 = __float2half_rn(w0), h1 = __float2half_rn(w1);
        __half l0 = __float2half_rn(w0 - __half2float(h0));
        __half l1 = __float2half_rn(w1 - __half2float(h1));
        __half2 hh = __halves2half2(h0, h1);
        __half2 ll = __halves2half2(l0, l1);
        hi[r] = *(unsigned*)&hh;
        lo[r] = *(unsigned*)&ll;
    }
    Wp[idx] = make_uint4(hi[0], hi[1], lo[0], lo[1]);
}

// ---------------- tensor-core GEMM: g_Ah = act(Xh) @ (W_hi + W_lo) ----------------
// block = 128 thr (4 warps), 64 rows/block, each warp 16 rows x 64 cols.
// One LDS.128 per (kt,nt) feeds both hi and lo MMAs.
template<int K, bool RELU>
__global__ __launch_bounds__(128) void k_gemm_mma(const __half* __restrict__ Xh,
                                                  const uint4* __restrict__ Wp) {
    __shared__ uint4 Wps[(K / 16) * 8 * 32];
    for (int i = threadIdx.x; i < (K / 16) * 8 * 32; i += 128) Wps[i] = Wp[i];
    __syncthreads();

    int warp = threadIdx.x >> 5, lane = threadIdx.x & 31;
    int g = lane >> 2, t = lane & 3;
    int row0 = blockIdx.x * 64 + warp * 16 + g;          // rows row0 and row0+8
    long rA = min(row0, N_NODES - 1);
    long rB = min(row0 + 8, N_NODES - 1);
    const __half* pa = Xh + rA * K + 2 * t;
    const __half* pb = Xh + rB * K + 2 * t;

    float acc[8][4];
#pragma unroll
    for (int nt = 0; nt < 8; nt++)
#pragma unroll
        for (int j = 0; j < 4; j++) acc[nt][j] = 0.0f;

    const __half2 zero2 = __float2half2_rn(0.0f);
#pragma unroll
    for (int kt = 0; kt < K / 16; kt++) {
        unsigned a0 = *(const unsigned*)(pa + kt * 16);
        unsigned a1 = *(const unsigned*)(pb + kt * 16);
        unsigned a2 = *(const unsigned*)(pa + kt * 16 + 8);
        unsigned a3 = *(const unsigned*)(pb + kt * 16 + 8);
        if (RELU) {
            __half2 v;
            v = __hmax2(*(__half2*)&a0, zero2); a0 = *(unsigned*)&v;
            v = __hmax2(*(__half2*)&a1, zero2); a1 = *(unsigned*)&v;
            v = __hmax2(*(__half2*)&a2, zero2); a2 = *(unsigned*)&v;
            v = __hmax2(*(__half2*)&a3, zero2); a3 = *(unsigned*)&v;
        }
#pragma unroll
        for (int nt = 0; nt < 8; nt++) {
            uint4 b = Wps[(kt * 8 + nt) * 32 + lane];    // {hi0,hi1,lo0,lo1}
            asm volatile(
                "mma.sync.aligned.m16n8k16.row.col.f32.f16.f16.f32 "
                "{%0,%1,%2,%3}, {%4,%5,%6,%7}, {%8,%9}, {%0,%1,%2,%3};"
                : "+f"(acc[nt][0]), "+f"(acc[nt][1]), "+f"(acc[nt][2]), "+f"(acc[nt][3])
                : "r"(a0), "r"(a1), "r"(a2), "r"(a3), "r"(b.x), "r"(b.y));
            asm volatile(
                "mma.sync.aligned.m16n8k16.row.col.f32.f16.f16.f32 "
                "{%0,%1,%2,%3}, {%4,%5,%6,%7}, {%8,%9}, {%0,%1,%2,%3};"
                : "+f"(acc[nt][0]), "+f"(acc[nt][1]), "+f"(acc[nt][2]), "+f"(acc[nt][3])
                : "r"(a0), "r"(a1), "r"(a2), "r"(a3), "r"(b.z), "r"(b.w));
        }
    }

    if (row0 < N_NODES) {
#pragma unroll
        for (int nt = 0; nt < 8; nt++) {
            __half2 h = __floats2half2_rn(acc[nt][0], acc[nt][1]);
            *(unsigned*)&g_Ah[(size_t)row0 * HID + nt * 8 + 2 * t] = *(unsigned*)&h;
        }
    }
    if (row0 + 8 < N_NODES) {
#pragma unroll
        for (int nt = 0; nt < 8; nt++) {
            __half2 h = __floats2half2_rn(acc[nt][2], acc[nt][3]);
            *(unsigned*)&g_Ah[(size_t)(row0 + 8) * HID + nt * 8 + 2 * t] = *(unsigned*)&h;
        }
    }
}

// ---------------- aggregation: one warp per TWO dst nodes ----------------
// 16 lanes per node, each lane covers 8B (uint2 = 4 cols). One gather LDG.64
// instruction serves two edges (one per half-warp) -> half the issue slots/edge.
__global__ __launch_bounds__(256) void k_agg(const float* __restrict__ bias) {
    int gw = (blockIdx.x * blockDim.x + threadIdx.x) >> 5;   // warp id
    int lane = threadIdx.x & 31;
    int half = lane >> 4, sub = lane & 15;
    int node = gw * 2 + half;
    if (node >= N_NODES) return;

    const uint2* A = (const uint2*)g_Ah;
    float dis = g_dis[node];
    float sn = dis * dis;
    float4 b4 = ((const float4*)bias)[sub];
    uint2 sv = A[(size_t)node * 16 + sub];
    float2 f0 = __half22float2(*(__half2*)&sv.x);
    float2 f1 = __half22float2(*(__half2*)&sv.y);
    float a0 = f0.x * sn + b4.x;
    float a1 = f0.y * sn + b4.y;
    float a2 = f1.x * sn + b4.z;
    float a3 = f1.y * sn + b4.w;

    int p   = g_off[node];
    int end = g_off[node + 1];
    for (; p + 2 <= end; p += 2) {
        int2 e0 = g_csr[p];
        int2 e1 = g_csr[p + 1];
        uint2 v0 = A[(size_t)e0.x * 16 + sub];
        uint2 v1 = A[(size_t)e1.x * 16 + sub];
        float n0 = __int_as_float(e0.y);
        float n1 = __int_as_float(e1.y);
        float2 g0 = __half22float2(*(__half2*)&v0.x);
        float2 g1 = __half22float2(*(__half2*)&v0.y);
        float2 g2 = __half22float2(*(__half2*)&v1.x);
        float2 g3 = __half22float2(*(__half2*)&v1.y);
        a0 += g0.x * n0; a1 += g0.y * n0; a2 += g1.x * n0; a3 += g1.y * n0;
        a0 += g2.x * n1; a1 += g2.y * n1; a2 += g3.x * n1; a3 += g3.y * n1;
    }
    if (p < end) {
        int2 e0 = g_csr[p];
        float n0 = __int_as_float(e0.y);
        uint2 v0 = A[(size_t)e0.x * 16 + sub];
        float2 g0 = __half22float2(*(__half2*)&v0.x);
        float2 g1 = __half22float2(*(__half2*)&v0.y);
        a0 += g0.x * n0; a1 += g0.y * n0; a2 += g1.x * n0; a3 += g1.y * n0;
    }

    __half2 o0 = __floats2half2_rn(a0, a1);
    __half2 o1 = __floats2half2_rn(a2, a3);
    uint2 ov;
    ov.x = *(unsigned*)&o0;
    ov.y = *(unsigned*)&o1;
    ((uint2*)g_Bh)[(size_t)node * 16 + sub] = ov;
}

// ---------------- global mean pool (batch is sorted int32) ----------------
__device__ __forceinline__ int lb_i32(const int* a, int n, int v) {
    int lo = 0, hi = n;
    while (lo < hi) {
        int mid = (lo + hi) >> 1;
        if (a[mid] < v) lo = mid + 1; else hi = mid;
    }
    return lo;
}

__global__ __launch_bounds__(256) void k_pool(const int* __restrict__ batch) {
    int g = blockIdx.x;
    int lo = lb_i32(batch, N_NODES, g);
    int hi = lb_i32(batch, N_NODES, g + 1);
    int c2 = threadIdx.x & 31;          // half2 column (2 cols per thread)
    int sub = threadIdx.x >> 5;         // 0..7
    const __half2* B2 = (const __half2*)g_Bh;
    float sx = 0.0f, sy = 0.0f;
    for (int i = lo + sub; i < hi; i += 8) {
        float2 v = __half22float2(B2[(size_t)i * 32 + c2]);
        sx += v.x; sy += v.y;
    }
    __shared__ float redx[256], redy[256];
    redx[threadIdx.x] = sx;
    redy[threadIdx.x] = sy;
    __syncthreads();
    if (sub == 0) {
        float tx = 0.0f, ty = 0.0f;
#pragma unroll
        for (int q = 0; q < 8; q++) { tx += redx[q * 32 + c2]; ty += redy[q * 32 + c2]; }
        float inv = 1.0f / fmaxf((float)(hi - lo), 1.0f);
        g_pooled[g * HID + 2 * c2]     = tx * inv;
        g_pooled[g * HID + 2 * c2 + 1] = ty * inv;
    }
}

// ---------------- classifier MLP ----------------
__global__ __launch_bounds__(64) void k_cls(const float* __restrict__ Wc1,
                                            const float* __restrict__ bc1,
                                            const float* __restrict__ Wc2,
                                            const float* __restrict__ bc2,
                                            float* __restrict__ out) {
    __shared__ float W1s[64 * 32];
    __shared__ float W2s[32 * 2];
    int t = threadIdx.x;
    for (int i = t; i < 64 * 32; i += 64) W1s[i] = Wc1[i];
    if (t < 64) W2s[t] = Wc2[t];
    __syncthreads();

    float p[64];
#pragma unroll
    for (int k = 0; k < 64; k++) p[k] = g_pooled[t * 64 + k];

    float h[32];
#pragma unroll
    for (int j = 0; j < 32; j++) {
        float s = bc1[j];
#pragma unroll
        for (int k = 0; k < 64; k++) s += p[k] * W1s[k * 32 + j];
        h[j] = fmaxf(s, 0.0f);
    }
#pragma unroll
    for (int o = 0; o < 2; o++) {
        float s = bc2[o];
#pragma unroll
        for (int j = 0; j < 32; j++) s += h[j] * W2s[j * 2 + o];
        out[t * 2 + o] = s;
    }
}

// ---------------- launch ----------------
extern "C" void kernel_launch(void* const* d_in, const int* in_sizes, int n_in,
                              void* d_out, int out_size) {
    const float* x     = (const float*)d_in[0];
    const int*   ei    = (const int*)d_in[1];
    const int*   batch = (const int*)d_in[2];
    const float* W1  = (const float*)d_in[3];
    const float* b1  = (const float*)d_in[4];
    const float* W2  = (const float*)d_in[5];
    const float* b2  = (const float*)d_in[6];
    const float* W3  = (const float*)d_in[7];
    const float* b3  = (const float*)d_in[8];
    const float* Wc1 = (const float*)d_in[9];
    const float* bc1 = (const float*)d_in[10];
    const float* Wc2 = (const float*)d_in[11];
    const float* bc2 = (const float*)d_in[12];
    float* out = (float*)d_out;

    const int TB = 256;
    const int gN  = (N_NODES + TB - 1) / TB;
    const int gE  = (N_EDGES + TB - 1) / TB;
    const int gW  = ((N_NODES + 1) / 2 * 32 + TB - 1) / TB;  // warp per 2 nodes
    const int gM  = (N_NODES + 63) / 64;                     // mma gemm grid (64 rows/blk)
    const int gX  = (N_NODES * IN_DIM / 4 + TB - 1) / TB;

    // DEVICE addresses of __device__ globals (host symbol is NOT the device ptr!)
    uint4 *wp1, *wp2, *wp3;
    __half *xh, *bh;
    cudaGetSymbolAddress((void**)&wp1, g_Wp1);
    cudaGetSymbolAddress((void**)&wp2, g_Wp2);
    cudaGetSymbolAddress((void**)&wp3, g_Wp3);
    cudaGetSymbolAddress((void**)&xh,  g_Xh);
    cudaGetSymbolAddress((void**)&bh,  g_Bh);

    // conversions
    k_xconv<<<gX, TB>>>(x);
    k_wconv<<<(IN_DIM * 16 + 127) / 128, 128>>>(W1, wp1, IN_DIM);
    k_wconv<<<(HID * 16 + 127) / 128, 128>>>(W2, wp2, HID);
    k_wconv<<<(HID * 16 + 127) / 128, 128>>>(W3, wp3, HID);

    // CSR-by-dst preprocessing
    k_zero<<<gN, TB>>>();
    k_count<<<gE, TB>>>(ei + N_EDGES);
    k_scan1<<<SCAN_NB, SCAN_B>>>();
    k_scan2<<<1, 128>>>();
    k_scan3<<<SCAN_NB, SCAN_B>>>();
    k_scatter<<<gE, TB>>>(ei);

    // layer 1
    k_gemm_mma<IN_DIM, false><<<gM, 128>>>(xh, wp1);
    k_agg<<<gW, TB>>>(b1);
    // layer 2
    k_gemm_mma<HID, true><<<gM, 128>>>(bh, wp2);
    k_agg<<<gW, TB>>>(b2);
    // layer 3
    k_gemm_mma<HID, true><<<gM, 128>>>(bh, wp3);
    k_agg<<<gW, TB>>>(b3);

    // pool + classifier
    k_pool<<<N_GRAPHS, 256>>>(batch);
    k_cls<<<1, 64>>>(Wc1, bc1, Wc2, bc2, out);
}

// round 14
// speedup vs baseline: 1.6356x; 1.0685x over previous
#include <cuda_runtime.h>
#include <cuda_fp16.h>

#define N_NODES 100000
#define N_EDGES 1600000
#define IN_DIM  128
#define HID     64
#define N_GRAPHS 64

#define SCAN_B 1024
#define SCAN_NB ((N_NODES + SCAN_B - 1) / SCAN_B)   // 98

// ---------------- static device scratch (no allocations allowed) ----------------
__device__ int   g_cnt[N_NODES];
__device__ int   g_cur[N_NODES];
__device__ int   g_off[N_NODES + 1];
__device__ float g_dis[N_NODES];
__device__ int   g_bsum[SCAN_NB];
__device__ int   g_bpre[SCAN_NB];
__device__ __align__(16) int2   g_csr[N_EDGES];                    // (src, norm-bits)
__device__ __align__(16) __half g_Xh[(size_t)N_NODES * IN_DIM];    // fp16 input features
__device__ __align__(16) __half g_Ah[(size_t)N_NODES * HID];       // GEMM out (messages)
__device__ __align__(16) __half g_Bh[(size_t)N_NODES * HID];       // agg out (layer act)
// interleaved split-fp16 weight fragments: one uint4 = {hi0, hi1, lo0, lo1} per (frag,lane)
__device__ __align__(16) uint4 g_Wp1[IN_DIM * 16];   // (K/16)*8*32 = K*16 uint4
__device__ __align__(16) uint4 g_Wp2[HID * 16];
__device__ __align__(16) uint4 g_Wp3[HID * 16];
__device__ float g_pooled[N_GRAPHS * HID];

// ---------------- preprocessing ----------------
__global__ __launch_bounds__(256) void k_zero() {
    int i = blockIdx.x * blockDim.x + threadIdx.x;
    if (i < N_NODES) { g_cnt[i] = 0; g_cur[i] = 0; }
}

__global__ __launch_bounds__(256) void k_count(const int* __restrict__ dst32) {
    int e = blockIdx.x * blockDim.x + threadIdx.x;
    if (e < N_EDGES) atomicAdd(&g_cnt[dst32[e]], 1);
}

__global__ __launch_bounds__(SCAN_B) void k_scan1() {
    int i = blockIdx.x * SCAN_B + threadIdx.x;
    int v = 0;
    if (i < N_NODES) {
        v = g_cnt[i];
        g_dis[i] = rsqrtf((float)(v + 1));
    }
    int lane = threadIdx.x & 31, wid = threadIdx.x >> 5;
    int s = v;
#pragma unroll
    for (int d = 16; d > 0; d >>= 1) s += __shfl_down_sync(~0u, s, d);
    __shared__ int wsum[32];
    if (lane == 0) wsum[wid] = s;
    __syncthreads();
    if (wid == 0) {
        int t = wsum[lane];
#pragma unroll
        for (int d = 16; d > 0; d >>= 1) t += __shfl_down_sync(~0u, t, d);
        if (lane == 0) g_bsum[blockIdx.x] = t;
    }
}

__global__ __launch_bounds__(128) void k_scan2() {
    __shared__ int sm[128];
    int t = threadIdx.x;
    int v = (t < SCAN_NB) ? g_bsum[t] : 0;
    sm[t] = v;
    __syncthreads();
    for (int d = 1; d < 128; d <<= 1) {
        int y = (t >= d) ? sm[t - d] : 0;
        __syncthreads();
        sm[t] += y;
        __syncthreads();
    }
    if (t < SCAN_NB) g_bpre[t] = sm[t] - v;
    if (t == 0) g_off[N_NODES] = N_EDGES;
}

__global__ __launch_bounds__(SCAN_B) void k_scan3() {
    int i = blockIdx.x * SCAN_B + threadIdx.x;
    int v = (i < N_NODES) ? g_cnt[i] : 0;
    int lane = threadIdx.x & 31, wid = threadIdx.x >> 5;
    int x = v;
#pragma unroll
    for (int d = 1; d < 32; d <<= 1) {
        int y = __shfl_up_sync(~0u, x, d);
        if (lane >= d) x += y;
    }
    __shared__ int wsum[32];
    if (lane == 31) wsum[wid] = x;
    __syncthreads();
    if (wid == 0) {
        int s = wsum[lane];
#pragma unroll
        for (int d = 1; d < 32; d <<= 1) {
            int y = __shfl_up_sync(~0u, s, d);
            if (lane >= d) s += y;
        }
        wsum[lane] = s;
    }
    __syncthreads();
    if (i < N_NODES)
        g_off[i] = (x - v) + (wid > 0 ? wsum[wid - 1] : 0) + g_bpre[blockIdx.x];
}

__global__ __launch_bounds__(256) void k_scatter(const int* __restrict__ ei) {
    int e = blockIdx.x * blockDim.x + threadIdx.x;
    if (e >= N_EDGES) return;
    int s = ei[e];
    int d = ei[N_EDGES + e];
    int pos = g_off[d] + atomicAdd(&g_cur[d], 1);
    float nrm = g_dis[s] * g_dis[d];
    g_csr[pos] = make_int2(s, __float_as_int(nrm));
}

// ---------------- conversions ----------------
__global__ __launch_bounds__(256) void k_xconv(const float* __restrict__ x) {
    int i = blockIdx.x * blockDim.x + threadIdx.x;       // one float4 -> one uint2
    const int total = N_NODES * IN_DIM / 4;
    if (i >= total) return;
    float4 v = ((const float4*)x)[i];
    __half2 h0 = __floats2half2_rn(v.x, v.y);
    __half2 h1 = __floats2half2_rn(v.z, v.w);
    uint2 pk;
    pk.x = *(unsigned*)&h0;
    pk.y = *(unsigned*)&h1;
    ((uint2*)g_Xh)[i] = pk;
}

// W fp32 [K,64] -> interleaved split-fp16 B-fragments (m16n8k16 layout)
__global__ __launch_bounds__(128) void k_wconv(const float* __restrict__ W,
                                               uint4* __restrict__ Wp, int K) {
    int idx = blockIdx.x * blockDim.x + threadIdx.x;
    if (idx >= K * 16) return;
    int lane = idx & 31;
    int nt   = (idx >> 5) & 7;
    int kt   = idx >> 8;
    int t = lane & 3, g = lane >> 2;
    int n = nt * 8 + g;
    unsigned hi[2], lo[2];
#pragma unroll
    for (int r = 0; r < 2; r++) {
        int k0 = kt * 16 + 2 * t + 8 * r;
        float w0 = W[k0 * 64 + n], w1 = W[(k0 + 1) * 64 + n];
        __half h0 = __float2half_rn(w0), h1 = __float2half_rn(w1);
        __half l0 = __float2half_rn(w0 - __half2float(h0));
        __half l1 = __float2half_rn(w1 - __half2float(h1));
        __half2 hh = __halves2half2(h0, h1);
        __half2 ll = __halves2half2(l0, l1);
        hi[r] = *(unsigned*)&hh;
        lo[r] = *(unsigned*)&ll;
    }
    Wp[idx] = make_uint4(hi[0], hi[1], lo[0], lo[1]);
}

// ---------------- tensor-core GEMM: g_Ah = act(Xh) @ (W_hi + W_lo) ----------------
// block = 128 thr (4 warps), 64 rows/block, each warp 16 rows x 64 cols.
// One LDS.128 per (kt,nt) feeds both hi and lo MMAs.
template<int K, bool RELU>
__global__ __launch_bounds__(128) void k_gemm_mma(const __half* __restrict__ Xh,
                                                  const uint4* __restrict__ Wp) {
    __shared__ uint4 Wps[(K / 16) * 8 * 32];
    for (int i = threadIdx.x; i < (K / 16) * 8 * 32; i += 128) Wps[i] = Wp[i];
    __syncthreads();

    int warp = threadIdx.x >> 5, lane = threadIdx.x & 31;
    int g = lane >> 2, t = lane & 3;
    int row0 = blockIdx.x * 64 + warp * 16 + g;          // rows row0 and row0+8
    long rA = min(row0, N_NODES - 1);
    long rB = min(row0 + 8, N_NODES - 1);
    const __half* pa = Xh + rA * K + 2 * t;
    const __half* pb = Xh + rB * K + 2 * t;

    float acc[8][4];
#pragma unroll
    for (int nt = 0; nt < 8; nt++)
#pragma unroll
        for (int j = 0; j < 4; j++) acc[nt][j] = 0.0f;

    const __half2 zero2 = __float2half2_rn(0.0f);
#pragma unroll
    for (int kt = 0; kt < K / 16; kt++) {
        unsigned a0 = *(const unsigned*)(pa + kt * 16);
        unsigned a1 = *(const unsigned*)(pb + kt * 16);
        unsigned a2 = *(const unsigned*)(pa + kt * 16 + 8);
        unsigned a3 = *(const unsigned*)(pb + kt * 16 + 8);
        if (RELU) {
            __half2 v;
            v = __hmax2(*(__half2*)&a0, zero2); a0 = *(unsigned*)&v;
            v = __hmax2(*(__half2*)&a1, zero2); a1 = *(unsigned*)&v;
            v = __hmax2(*(__half2*)&a2, zero2); a2 = *(unsigned*)&v;
            v = __hmax2(*(__half2*)&a3, zero2); a3 = *(unsigned*)&v;
        }
#pragma unroll
        for (int nt = 0; nt < 8; nt++) {
            uint4 b = Wps[(kt * 8 + nt) * 32 + lane];    // {hi0,hi1,lo0,lo1}
            asm volatile(
                "mma.sync.aligned.m16n8k16.row.col.f32.f16.f16.f32 "
                "{%0,%1,%2,%3}, {%4,%5,%6,%7}, {%8,%9}, {%0,%1,%2,%3};"
                : "+f"(acc[nt][0]), "+f"(acc[nt][1]), "+f"(acc[nt][2]), "+f"(acc[nt][3])
                : "r"(a0), "r"(a1), "r"(a2), "r"(a3), "r"(b.x), "r"(b.y));
            asm volatile(
                "mma.sync.aligned.m16n8k16.row.col.f32.f16.f16.f32 "
                "{%0,%1,%2,%3}, {%4,%5,%6,%7}, {%8,%9}, {%0,%1,%2,%3};"
                : "+f"(acc[nt][0]), "+f"(acc[nt][1]), "+f"(acc[nt][2]), "+f"(acc[nt][3])
                : "r"(a0), "r"(a1), "r"(a2), "r"(a3), "r"(b.z), "r"(b.w));
        }
    }

    if (row0 < N_NODES) {
#pragma unroll
        for (int nt = 0; nt < 8; nt++) {
            __half2 h = __floats2half2_rn(acc[nt][0], acc[nt][1]);
            *(unsigned*)&g_Ah[(size_t)row0 * HID + nt * 8 + 2 * t] = *(unsigned*)&h;
        }
    }
    if (row0 + 8 < N_NODES) {
#pragma unroll
        for (int nt = 0; nt < 8; nt++) {
            __half2 h = __floats2half2_rn(acc[nt][2], acc[nt][3]);
            *(unsigned*)&g_Ah[(size_t)(row0 + 8) * HID + nt * 8 + 2 * t] = *(unsigned*)&h;
        }
    }
}

// ---------------- aggregation: one warp per FOUR dst nodes ----------------
// 8 lanes per node, each lane covers 16B (uint4 = 8 cols). One warp-wide
// LDG.128 serves four edges (one per quarter-warp).
__global__ __launch_bounds__(256) void k_agg(const float* __restrict__ bias) {
    int gw = (blockIdx.x * blockDim.x + threadIdx.x) >> 5;   // warp id
    int lane = threadIdx.x & 31;
    int q = lane >> 3, sub = lane & 7;
    int node = gw * 4 + q;
    if (node >= N_NODES) return;

    const uint4* A = (const uint4*)g_Ah;                     // 8 uint4 per row
    float dis = g_dis[node];
    float sn = dis * dis;
    float4 b0 = ((const float4*)bias)[sub * 2];
    float4 b1 = ((const float4*)bias)[sub * 2 + 1];
    uint4 sv = A[(size_t)node * 8 + sub];
    float2 s0 = __half22float2(*(__half2*)&sv.x);
    float2 s1 = __half22float2(*(__half2*)&sv.y);
    float2 s2 = __half22float2(*(__half2*)&sv.z);
    float2 s3 = __half22float2(*(__half2*)&sv.w);
    float a0 = s0.x * sn + b0.x;
    float a1 = s0.y * sn + b0.y;
    float a2 = s1.x * sn + b0.z;
    float a3 = s1.y * sn + b0.w;
    float a4 = s2.x * sn + b1.x;
    float a5 = s2.y * sn + b1.y;
    float a6 = s3.x * sn + b1.z;
    float a7 = s3.y * sn + b1.w;

    int p   = g_off[node];
    int end = g_off[node + 1];
    for (; p + 2 <= end; p += 2) {
        int2 e0 = g_csr[p];
        int2 e1 = g_csr[p + 1];
        uint4 v0 = A[(size_t)e0.x * 8 + sub];
        uint4 v1 = A[(size_t)e1.x * 8 + sub];
        float n0 = __int_as_float(e0.y);
        float n1 = __int_as_float(e1.y);
        float2 g0, g1, g2, g3;
        g0 = __half22float2(*(__half2*)&v0.x);
        g1 = __half22float2(*(__half2*)&v0.y);
        g2 = __half22float2(*(__half2*)&v0.z);
        g3 = __half22float2(*(__half2*)&v0.w);
        a0 += g0.x * n0; a1 += g0.y * n0; a2 += g1.x * n0; a3 += g1.y * n0;
        a4 += g2.x * n0; a5 += g2.y * n0; a6 += g3.x * n0; a7 += g3.y * n0;
        g0 = __half22float2(*(__half2*)&v1.x);
        g1 = __half22float2(*(__half2*)&v1.y);
        g2 = __half22float2(*(__half2*)&v1.z);
        g3 = __half22float2(*(__half2*)&v1.w);
        a0 += g0.x * n1; a1 += g0.y * n1; a2 += g1.x * n1; a3 += g1.y * n1;
        a4 += g2.x * n1; a5 += g2.y * n1; a6 += g3.x * n1; a7 += g3.y * n1;
    }
    if (p < end) {
        int2 e0 = g_csr[p];
        float n0 = __int_as_float(e0.y);
        uint4 v0 = A[(size_t)e0.x * 8 + sub];
        float2 g0 = __half22float2(*(__half2*)&v0.x);
        float2 g1 = __half22float2(*(__half2*)&v0.y);
        float2 g2 = __half22float2(*(__half2*)&v0.z);
        float2 g3 = __half22float2(*(__half2*)&v0.w);
        a0 += g0.x * n0; a1 += g0.y * n0; a2 += g1.x * n0; a3 += g1.y * n0;
        a4 += g2.x * n0; a5 += g2.y * n0; a6 += g3.x * n0; a7 += g3.y * n0;
    }

    __half2 o0 = __floats2half2_rn(a0, a1);
    __half2 o1 = __floats2half2_rn(a2, a3);
    __half2 o2 = __floats2half2_rn(a4, a5);
    __half2 o3 = __floats2half2_rn(a6, a7);
    uint4 ov;
    ov.x = *(unsigned*)&o0;
    ov.y = *(unsigned*)&o1;
    ov.z = *(unsigned*)&o2;
    ov.w = *(unsigned*)&o3;
    ((uint4*)g_Bh)[(size_t)node * 8 + sub] = ov;
}

// ---------------- global mean pool (batch is sorted int32) ----------------
__device__ __forceinline__ int lb_i32(const int* a, int n, int v) {
    int lo = 0, hi = n;
    while (lo < hi) {
        int mid = (lo + hi) >> 1;
        if (a[mid] < v) lo = mid + 1; else hi = mid;
    }
    return lo;
}

__global__ __launch_bounds__(256) void k_pool(const int* __restrict__ batch) {
    int g = blockIdx.x;
    int lo = lb_i32(batch, N_NODES, g);
    int hi = lb_i32(batch, N_NODES, g + 1);
    int c2 = threadIdx.x & 31;          // half2 column (2 cols per thread)
    int sub = threadIdx.x >> 5;         // 0..7
    const __half2* B2 = (const __half2*)g_Bh;
    float sx = 0.0f, sy = 0.0f;
    for (int i = lo + sub; i < hi; i += 8) {
        float2 v = __half22float2(B2[(size_t)i * 32 + c2]);
        sx += v.x; sy += v.y;
    }
    __shared__ float redx[256], redy[256];
    redx[threadIdx.x] = sx;
    redy[threadIdx.x] = sy;
    __syncthreads();
    if (sub == 0) {
        float tx = 0.0f, ty = 0.0f;
#pragma unroll
        for (int q = 0; q < 8; q++) { tx += redx[q * 32 + c2]; ty += redy[q * 32 + c2]; }
        float inv = 1.0f / fmaxf((float)(hi - lo), 1.0f);
        g_pooled[g * HID + 2 * c2]     = tx * inv;
        g_pooled[g * HID + 2 * c2 + 1] = ty * inv;
    }
}

// ---------------- classifier MLP ----------------
__global__ __launch_bounds__(64) void k_cls(const float* __restrict__ Wc1,
                                            const float* __restrict__ bc1,
                                            const float* __restrict__ Wc2,
                                            const float* __restrict__ bc2,
                                            float* __restrict__ out) {
    __shared__ float W1s[64 * 32];
    __shared__ float W2s[32 * 2];
    int t = threadIdx.x;
    for (int i = t; i < 64 * 32; i += 64) W1s[i] = Wc1[i];
    if (t < 64) W2s[t] = Wc2[t];
    __syncthreads();

    float p[64];
#pragma unroll
    for (int k = 0; k < 64; k++) p[k] = g_pooled[t * 64 + k];

    float h[32];
#pragma unroll
    for (int j = 0; j < 32; j++) {
        float s = bc1[j];
#pragma unroll
        for (int k = 0; k < 64; k++) s += p[k] * W1s[k * 32 + j];
        h[j] = fmaxf(s, 0.0f);
    }
#pragma unroll
    for (int o = 0; o < 2; o++) {
        float s = bc2[o];
#pragma unroll
        for (int j = 0; j < 32; j++) s += h[j] * W2s[j * 2 + o];
        out[t * 2 + o] = s;
    }
}

// ---------------- launch ----------------
extern "C" void kernel_launch(void* const* d_in, const int* in_sizes, int n_in,
                              void* d_out, int out_size) {
    const float* x     = (const float*)d_in[0];
    const int*   ei    = (const int*)d_in[1];
    const int*   batch = (const int*)d_in[2];
    const float* W1  = (const float*)d_in[3];
    const float* b1  = (const float*)d_in[4];
    const float* W2  = (const float*)d_in[5];
    const float* b2  = (const float*)d_in[6];
    const float* W3  = (const float*)d_in[7];
    const float* b3  = (const float*)d_in[8];
    const float* Wc1 = (const float*)d_in[9];
    const float* bc1 = (const float*)d_in[10];
    const float* Wc2 = (const float*)d_in[11];
    const float* bc2 = (const float*)d_in[12];
    float* out = (float*)d_out;

    const int TB = 256;
    const int gN  = (N_NODES + TB - 1) / TB;
    const int gE  = (N_EDGES + TB - 1) / TB;
    const int gW  = ((N_NODES + 3) / 4 * 32 + TB - 1) / TB;  // warp per 4 nodes
    const int gM  = (N_NODES + 63) / 64;                     // mma gemm grid (64 rows/blk)
    const int gX  = (N_NODES * IN_DIM / 4 + TB - 1) / TB;

    // DEVICE addresses of __device__ globals (host symbol is NOT the device ptr!)
    uint4 *wp1, *wp2, *wp3;
    __half *xh, *bh;
    cudaGetSymbolAddress((void**)&wp1, g_Wp1);
    cudaGetSymbolAddress((void**)&wp2, g_Wp2);
    cudaGetSymbolAddress((void**)&wp3, g_Wp3);
    cudaGetSymbolAddress((void**)&xh,  g_Xh);
    cudaGetSymbolAddress((void**)&bh,  g_Bh);

    // conversions
    k_xconv<<<gX, TB>>>(x);
    k_wconv<<<(IN_DIM * 16 + 127) / 128, 128>>>(W1, wp1, IN_DIM);
    k_wconv<<<(HID * 16 + 127) / 128, 128>>>(W2, wp2, HID);
    k_wconv<<<(HID * 16 + 127) / 128, 128>>>(W3, wp3, HID);

    // CSR-by-dst preprocessing
    k_zero<<<gN, TB>>>();
    k_count<<<gE, TB>>>(ei + N_EDGES);
    k_scan1<<<SCAN_NB, SCAN_B>>>();
    k_scan2<<<1, 128>>>();
    k_scan3<<<SCAN_NB, SCAN_B>>>();
    k_scatter<<<gE, TB>>>(ei);

    // layer 1
    k_gemm_mma<IN_DIM, false><<<gM, 128>>>(xh, wp1);
    k_agg<<<gW, TB>>>(b1);
    // layer 2
    k_gemm_mma<HID, true><<<gM, 128>>>(bh, wp2);
    k_agg<<<gW, TB>>>(b2);
    // layer 3
    k_gemm_mma<HID, true><<<gM, 128>>>(bh, wp3);
    k_agg<<<gW, TB>>>(b3);

    // pool + classifier
    k_pool<<<N_GRAPHS, 256>>>(batch);
    k_cls<<<1, 64>>>(Wc1, bc1, Wc2, bc2, out);
}

// round 16
// speedup vs baseline: 1.7145x; 1.0482x over previous
#include <cuda_runtime.h>
#include <cuda_fp16.h>

#define N_NODES 100000
#define N_EDGES 1600000
#define IN_DIM  128
#define HID     64
#define N_GRAPHS 64

#define SCAN_B 1024
#define SCAN_NB ((N_NODES + SCAN_B - 1) / SCAN_B)   // 98

// ---------------- static device scratch (no allocations allowed) ----------------
__device__ int   g_cnt[N_NODES];
__device__ int   g_cur[N_NODES];
__device__ int   g_off[N_NODES + 1];
__device__ float g_dis[N_NODES];
__device__ int   g_bsum[SCAN_NB];
__device__ int   g_bpre[SCAN_NB];
__device__ __align__(16) int2   g_csr[N_EDGES];                    // (src, norm as half2)
__device__ __align__(16) __half g_Xh[(size_t)N_NODES * IN_DIM];    // fp16 input features
__device__ __align__(16) __half g_Ah[(size_t)N_NODES * HID];       // GEMM out (messages)
__device__ __align__(16) __half g_Bh[(size_t)N_NODES * HID];       // agg out (layer act)
// interleaved split-fp16 weight fragments: one uint4 = {hi0, hi1, lo0, lo1} per (frag,lane)
__device__ __align__(16) uint4 g_Wp1[IN_DIM * 16];   // (K/16)*8*32 = K*16 uint4
__device__ __align__(16) uint4 g_Wp2[HID * 16];
__device__ __align__(16) uint4 g_Wp3[HID * 16];
__device__ float g_pooled[N_GRAPHS * HID];

// ---------------- preprocessing ----------------
__global__ __launch_bounds__(256) void k_zero() {
    int i = blockIdx.x * blockDim.x + threadIdx.x;
    if (i < N_NODES) { g_cnt[i] = 0; g_cur[i] = 0; }
}

__global__ __launch_bounds__(256) void k_count(const int* __restrict__ dst32) {
    int e = blockIdx.x * blockDim.x + threadIdx.x;
    if (e < N_EDGES) atomicAdd(&g_cnt[dst32[e]], 1);
}

__global__ __launch_bounds__(SCAN_B) void k_scan1() {
    int i = blockIdx.x * SCAN_B + threadIdx.x;
    int v = 0;
    if (i < N_NODES) {
        v = g_cnt[i];
        g_dis[i] = rsqrtf((float)(v + 1));
    }
    int lane = threadIdx.x & 31, wid = threadIdx.x >> 5;
    int s = v;
#pragma unroll
    for (int d = 16; d > 0; d >>= 1) s += __shfl_down_sync(~0u, s, d);
    __shared__ int wsum[32];
    if (lane == 0) wsum[wid] = s;
    __syncthreads();
    if (wid == 0) {
        int t = wsum[lane];
#pragma unroll
        for (int d = 16; d > 0; d >>= 1) t += __shfl_down_sync(~0u, t, d);
        if (lane == 0) g_bsum[blockIdx.x] = t;
    }
}

__global__ __launch_bounds__(128) void k_scan2() {
    __shared__ int sm[128];
    int t = threadIdx.x;
    int v = (t < SCAN_NB) ? g_bsum[t] : 0;
    sm[t] = v;
    __syncthreads();
    for (int d = 1; d < 128; d <<= 1) {
        int y = (t >= d) ? sm[t - d] : 0;
        __syncthreads();
        sm[t] += y;
        __syncthreads();
    }
    if (t < SCAN_NB) g_bpre[t] = sm[t] - v;
    if (t == 0) g_off[N_NODES] = N_EDGES;
}

__global__ __launch_bounds__(SCAN_B) void k_scan3() {
    int i = blockIdx.x * SCAN_B + threadIdx.x;
    int v = (i < N_NODES) ? g_cnt[i] : 0;
    int lane = threadIdx.x & 31, wid = threadIdx.x >> 5;
    int x = v;
#pragma unroll
    for (int d = 1; d < 32; d <<= 1) {
        int y = __shfl_up_sync(~0u, x, d);
        if (lane >= d) x += y;
    }
    __shared__ int wsum[32];
    if (lane == 31) wsum[wid] = x;
    __syncthreads();
    if (wid == 0) {
        int s = wsum[lane];
#pragma unroll
        for (int d = 1; d < 32; d <<= 1) {
            int y = __shfl_up_sync(~0u, s, d);
            if (lane >= d) s += y;
        }
        wsum[lane] = s;
    }
    __syncthreads();
    if (i < N_NODES)
        g_off[i] = (x - v) + (wid > 0 ? wsum[wid - 1] : 0) + g_bpre[blockIdx.x];
}

__global__ __launch_bounds__(256) void k_scatter(const int* __restrict__ ei) {
    int e = blockIdx.x * blockDim.x + threadIdx.x;
    if (e >= N_EDGES) return;
    int s = ei[e];
    int d = ei[N_EDGES + e];
    int pos = g_off[d] + atomicAdd(&g_cur[d], 1);
    float nrm = g_dis[s] * g_dis[d];
    __half2 nh = __float2half2_rn(nrm);          // norm packed as half2
    g_csr[pos] = make_int2(s, *(int*)&nh);
}

// ---------------- conversions ----------------
__global__ __launch_bounds__(256) void k_xconv(const float* __restrict__ x) {
    int i = blockIdx.x * blockDim.x + threadIdx.x;       // one float4 -> one uint2
    const int total = N_NODES * IN_DIM / 4;
    if (i >= total) return;
    float4 v = ((const float4*)x)[i];
    __half2 h0 = __floats2half2_rn(v.x, v.y);
    __half2 h1 = __floats2half2_rn(v.z, v.w);
    uint2 pk;
    pk.x = *(unsigned*)&h0;
    pk.y = *(unsigned*)&h1;
    ((uint2*)g_Xh)[i] = pk;
}

// All three W fp32 [K,64] -> interleaved split-fp16 B-fragments in ONE launch.
// thread idx space: [0, IN_DIM*16) -> W1, then HID*16 -> W2, then HID*16 -> W3.
__global__ __launch_bounds__(128) void k_wconv3(const float* __restrict__ W1,
                                                const float* __restrict__ W2,
                                                const float* __restrict__ W3,
                                                uint4* __restrict__ Wp1,
                                                uint4* __restrict__ Wp2,
                                                uint4* __restrict__ Wp3) {
    int tidg = blockIdx.x * blockDim.x + threadIdx.x;
    const float* W; uint4* Wp; int idx;
    if (tidg < IN_DIM * 16)                       { W = W1; Wp = Wp1; idx = tidg; }
    else if (tidg < IN_DIM * 16 + HID * 16)       { W = W2; Wp = Wp2; idx = tidg - IN_DIM * 16; }
    else if (tidg < IN_DIM * 16 + 2 * HID * 16)   { W = W3; Wp = Wp3; idx = tidg - IN_DIM * 16 - HID * 16; }
    else return;
    int lane = idx & 31;
    int nt   = (idx >> 5) & 7;
    int kt   = idx >> 8;
    int t = lane & 3, g = lane >> 2;
    int n = nt * 8 + g;
    unsigned hi[2], lo[2];
#pragma unroll
    for (int r = 0; r < 2; r++) {
        int k0 = kt * 16 + 2 * t + 8 * r;
        float w0 = W[k0 * 64 + n], w1 = W[(k0 + 1) * 64 + n];
        __half h0 = __float2half_rn(w0), h1 = __float2half_rn(w1);
        __half l0 = __float2half_rn(w0 - __half2float(h0));
        __half l1 = __float2half_rn(w1 - __half2float(h1));
        __half2 hh = __halves2half2(h0, h1);
        __half2 ll = __halves2half2(l0, l1);
        hi[r] = *(unsigned*)&hh;
        lo[r] = *(unsigned*)&ll;
    }
    Wp[idx] = make_uint4(hi[0], hi[1], lo[0], lo[1]);
}

// ---------------- tensor-core GEMM: g_Ah = act(Xh) @ (W_hi + W_lo) ----------------
template<int K, bool RELU>
__global__ __launch_bounds__(128) void k_gemm_mma(const __half* __restrict__ Xh,
                                                  const uint4* __restrict__ Wp) {
    __shared__ uint4 Wps[(K / 16) * 8 * 32];
    for (int i = threadIdx.x; i < (K / 16) * 8 * 32; i += 128) Wps[i] = Wp[i];
    __syncthreads();

    int warp = threadIdx.x >> 5, lane = threadIdx.x & 31;
    int g = lane >> 2, t = lane & 3;
    int row0 = blockIdx.x * 64 + warp * 16 + g;          // rows row0 and row0+8
    long rA = min(row0, N_NODES - 1);
    long rB = min(row0 + 8, N_NODES - 1);
    const __half* pa = Xh + rA * K + 2 * t;
    const __half* pb = Xh + rB * K + 2 * t;

    float acc[8][4];
#pragma unroll
    for (int nt = 0; nt < 8; nt++)
#pragma unroll
        for (int j = 0; j < 4; j++) acc[nt][j] = 0.0f;

    const __half2 zero2 = __float2half2_rn(0.0f);
#pragma unroll
    for (int kt = 0; kt < K / 16; kt++) {
        unsigned a0 = *(const unsigned*)(pa + kt * 16);
        unsigned a1 = *(const unsigned*)(pb + kt * 16);
        unsigned a2 = *(const unsigned*)(pa + kt * 16 + 8);
        unsigned a3 = *(const unsigned*)(pb + kt * 16 + 8);
        if (RELU) {
            __half2 v;
            v = __hmax2(*(__half2*)&a0, zero2); a0 = *(unsigned*)&v;
            v = __hmax2(*(__half2*)&a1, zero2); a1 = *(unsigned*)&v;
            v = __hmax2(*(__half2*)&a2, zero2); a2 = *(unsigned*)&v;
            v = __hmax2(*(__half2*)&a3, zero2); a3 = *(unsigned*)&v;
        }
#pragma unroll
        for (int nt = 0; nt < 8; nt++) {
            uint4 b = Wps[(kt * 8 + nt) * 32 + lane];    // {hi0,hi1,lo0,lo1}
            asm volatile(
                "mma.sync.aligned.m16n8k16.row.col.f32.f16.f16.f32 "
                "{%0,%1,%2,%3}, {%4,%5,%6,%7}, {%8,%9}, {%0,%1,%2,%3};"
                : "+f"(acc[nt][0]), "+f"(acc[nt][1]), "+f"(acc[nt][2]), "+f"(acc[nt][3])
                : "r"(a0), "r"(a1), "r"(a2), "r"(a3), "r"(b.x), "r"(b.y));
            asm volatile(
                "mma.sync.aligned.m16n8k16.row.col.f32.f16.f16.f32 "
                "{%0,%1,%2,%3}, {%4,%5,%6,%7}, {%8,%9}, {%0,%1,%2,%3};"
                : "+f"(acc[nt][0]), "+f"(acc[nt][1]), "+f"(acc[nt][2]), "+f"(acc[nt][3])
                : "r"(a0), "r"(a1), "r"(a2), "r"(a3), "r"(b.z), "r"(b.w));
        }
    }

    if (row0 < N_NODES) {
#pragma unroll
        for (int nt = 0; nt < 8; nt++) {
            __half2 h = __floats2half2_rn(acc[nt][0], acc[nt][1]);
            *(unsigned*)&g_Ah[(size_t)row0 * HID + nt * 8 + 2 * t] = *(unsigned*)&h;
        }
    }
    if (row0 + 8 < N_NODES) {
#pragma unroll
        for (int nt = 0; nt < 8; nt++) {
            __half2 h = __floats2half2_rn(acc[nt][2], acc[nt][3]);
            *(unsigned*)&g_Ah[(size_t)(row0 + 8) * HID + nt * 8 + 2 * t] = *(unsigned*)&h;
        }
    }
}

// ---------------- aggregation: one warp per FOUR dst nodes, fp16 HFMA2 accum ----------------
// 8 lanes per node, each lane covers 16B (uint4 = 4 half2 = 8 cols).
// Edge sum in fp16 (4 HFMA2/edge/lane); self-loop + bias added in fp32 at the end.
__global__ __launch_bounds__(256) void k_agg(const float* __restrict__ bias) {
    int gw = (blockIdx.x * blockDim.x + threadIdx.x) >> 5;   // warp id
    int lane = threadIdx.x & 31;
    int q = lane >> 3, sub = lane & 7;
    int node = gw * 4 + q;
    if (node >= N_NODES) return;

    const uint4* A = (const uint4*)g_Ah;                     // 8 uint4 per row
    __half2 c0 = __float2half2_rn(0.0f);
    __half2 c1 = c0, c2 = c0, c3 = c0;

    int p   = g_off[node];
    int end = g_off[node + 1];
    for (; p + 2 <= end; p += 2) {
        int2 e0 = g_csr[p];
        int2 e1 = g_csr[p + 1];
        uint4 v0 = A[(size_t)e0.x * 8 + sub];
        uint4 v1 = A[(size_t)e1.x * 8 + sub];
        __half2 n0 = *(__half2*)&e0.y;
        __half2 n1 = *(__half2*)&e1.y;
        c0 = __hfma2(*(__half2*)&v0.x, n0, c0);
        c1 = __hfma2(*(__half2*)&v0.y, n0, c1);
        c2 = __hfma2(*(__half2*)&v0.z, n0, c2);
        c3 = __hfma2(*(__half2*)&v0.w, n0, c3);
        c0 = __hfma2(*(__half2*)&v1.x, n1, c0);
        c1 = __hfma2(*(__half2*)&v1.y, n1, c1);
        c2 = __hfma2(*(__half2*)&v1.z, n1, c2);
        c3 = __hfma2(*(__half2*)&v1.w, n1, c3);
    }
    if (p < end) {
        int2 e0 = g_csr[p];
        uint4 v0 = A[(size_t)e0.x * 8 + sub];
        __half2 n0 = *(__half2*)&e0.y;
        c0 = __hfma2(*(__half2*)&v0.x, n0, c0);
        c1 = __hfma2(*(__half2*)&v0.y, n0, c1);
        c2 = __hfma2(*(__half2*)&v0.z, n0, c2);
        c3 = __hfma2(*(__half2*)&v0.w, n0, c3);
    }

    // self-loop + bias in fp32
    float dis = g_dis[node];
    float sn = dis * dis;
    float4 b0 = ((const float4*)bias)[sub * 2];
    float4 b1 = ((const float4*)bias)[sub * 2 + 1];
    uint4 sv = A[(size_t)node * 8 + sub];
    float2 s0 = __half22float2(*(__half2*)&sv.x);
    float2 s1 = __half22float2(*(__half2*)&sv.y);
    float2 s2 = __half22float2(*(__half2*)&sv.z);
    float2 s3 = __half22float2(*(__half2*)&sv.w);
    float2 e0f = __half22float2(c0);
    float2 e1f = __half22float2(c1);
    float2 e2f = __half22float2(c2);
    float2 e3f = __half22float2(c3);
    float a0 = e0f.x + s0.x * sn + b0.x;
    float a1 = e0f.y + s0.y * sn + b0.y;
    float a2 = e1f.x + s1.x * sn + b0.z;
    float a3 = e1f.y + s1.y * sn + b0.w;
    float a4 = e2f.x + s2.x * sn + b1.x;
    float a5 = e2f.y + s2.y * sn + b1.y;
    float a6 = e3f.x + s3.x * sn + b1.z;
    float a7 = e3f.y + s3.y * sn + b1.w;

    __half2 o0 = __floats2half2_rn(a0, a1);
    __half2 o1 = __floats2half2_rn(a2, a3);
    __half2 o2 = __floats2half2_rn(a4, a5);
    __half2 o3 = __floats2half2_rn(a6, a7);
    uint4 ov;
    ov.x = *(unsigned*)&o0;
    ov.y = *(unsigned*)&o1;
    ov.z = *(unsigned*)&o2;
    ov.w = *(unsigned*)&o3;
    ((uint4*)g_Bh)[(size_t)node * 8 + sub] = ov;
}

// ---------------- global mean pool (batch is sorted int32) ----------------
__device__ __forceinline__ int lb_i32(const int* a, int n, int v) {
    int lo = 0, hi = n;
    while (lo < hi) {
        int mid = (lo + hi) >> 1;
        if (a[mid] < v) lo = mid + 1; else hi = mid;
    }
    return lo;
}

__global__ __launch_bounds__(256) void k_pool(const int* __restrict__ batch) {
    int g = blockIdx.x;
    int lo = lb_i32(batch, N_NODES, g);
    int hi = lb_i32(batch, N_NODES, g + 1);
    int c2 = threadIdx.x & 31;          // half2 column (2 cols per thread)
    int sub = threadIdx.x >> 5;         // 0..7
    const __half2* B2 = (const __half2*)g_Bh;
    float sx = 0.0f, sy = 0.0f;
    for (int i = lo + sub; i < hi; i += 8) {
        float2 v = __half22float2(B2[(size_t)i * 32 + c2]);
        sx += v.x; sy += v.y;
    }
    __shared__ float redx[256], redy[256];
    redx[threadIdx.x] = sx;
    redy[threadIdx.x] = sy;
    __syncthreads();
    if (sub == 0) {
        float tx = 0.0f, ty = 0.0f;
#pragma unroll
        for (int q = 0; q < 8; q++) { tx += redx[q * 32 + c2]; ty += redy[q * 32 + c2]; }
        float inv = 1.0f / fmaxf((float)(hi - lo), 1.0f);
        g_pooled[g * HID + 2 * c2]     = tx * inv;
        g_pooled[g * HID + 2 * c2 + 1] = ty * inv;
    }
}

// ---------------- classifier MLP ----------------
__global__ __launch_bounds__(64) void k_cls(const float* __restrict__ Wc1,
                                            const float* __restrict__ bc1,
                                            const float* __restrict__ Wc2,
                                            const float* __restrict__ bc2,
                                            float* __restrict__ out) {
    __shared__ float W1s[64 * 32];
    __shared__ float W2s[32 * 2];
    int t = threadIdx.x;
    for (int i = t; i < 64 * 32; i += 64) W1s[i] = Wc1[i];
    if (t < 64) W2s[t] = Wc2[t];
    __syncthreads();

    float p[64];
#pragma unroll
    for (int k = 0; k < 64; k++) p[k] = g_pooled[t * 64 + k];

    float h[32];
#pragma unroll
    for (int j = 0; j < 32; j++) {
        float s = bc1[j];
#pragma unroll
        for (int k = 0; k < 64; k++) s += p[k] * W1s[k * 32 + j];
        h[j] = fmaxf(s, 0.0f);
    }
#pragma unroll
    for (int o = 0; o < 2; o++) {
        float s = bc2[o];
#pragma unroll
        for (int j = 0; j < 32; j++) s += h[j] * W2s[j * 2 + o];
        out[t * 2 + o] = s;
    }
}

// ---------------- launch ----------------
extern "C" void kernel_launch(void* const* d_in, const int* in_sizes, int n_in,
                              void* d_out, int out_size) {
    const float* x     = (const float*)d_in[0];
    const int*   ei    = (const int*)d_in[1];
    const int*   batch = (const int*)d_in[2];
    const float* W1  = (const float*)d_in[3];
    const float* b1  = (const float*)d_in[4];
    const float* W2  = (const float*)d_in[5];
    const float* b2  = (const float*)d_in[6];
    const float* W3  = (const float*)d_in[7];
    const float* b3  = (const float*)d_in[8];
    const float* Wc1 = (const float*)d_in[9];
    const float* bc1 = (const float*)d_in[10];
    const float* Wc2 = (const float*)d_in[11];
    const float* bc2 = (const float*)d_in[12];
    float* out = (float*)d_out;

    const int TB = 256;
    const int gN  = (N_NODES + TB - 1) / TB;
    const int gE  = (N_EDGES + TB - 1) / TB;
    const int gW  = ((N_NODES + 3) / 4 * 32 + TB - 1) / TB;  // warp per 4 nodes
    const int gM  = (N_NODES + 63) / 64;                     // mma gemm grid (64 rows/blk)
    const int gX  = (N_NODES * IN_DIM / 4 + TB - 1) / TB;
    const int gWC = (IN_DIM * 16 + 2 * HID * 16 + 127) / 128;

    // DEVICE addresses of __device__ globals (host symbol is NOT the device ptr!)
    uint4 *wp1, *wp2, *wp3;
    __half *xh, *bh;
    cudaGetSymbolAddress((void**)&wp1, g_Wp1);
    cudaGetSymbolAddress((void**)&wp2, g_Wp2);
    cudaGetSymbolAddress((void**)&wp3, g_Wp3);
    cudaGetSymbolAddress((void**)&xh,  g_Xh);
    cudaGetSymbolAddress((void**)&bh,  g_Bh);

    // conversions
    k_xconv<<<gX, TB>>>(x);
    k_wconv3<<<gWC, 128>>>(W1, W2, W3, wp1, wp2, wp3);

    // CSR-by-dst preprocessing
    k_zero<<<gN, TB>>>();
    k_count<<<gE, TB>>>(ei + N_EDGES);
    k_scan1<<<SCAN_NB, SCAN_B>>>();
    k_scan2<<<1, 128>>>();
    k_scan3<<<SCAN_NB, SCAN_B>>>();
    k_scatter<<<gE, TB>>>(ei);

    // layer 1
    k_gemm_mma<IN_DIM, false><<<gM, 128>>>(xh, wp1);
    k_agg<<<gW, TB>>>(b1);
    // layer 2
    k_gemm_mma<HID, true><<<gM, 128>>>(bh, wp2);
    k_agg<<<gW, TB>>>(b2);
    // layer 3
    k_gemm_mma<HID, true><<<gM, 128>>>(bh, wp3);
    k_agg<<<gW, TB>>>(b3);

    // pool + classifier
    k_pool<<<N_GRAPHS, 256>>>(batch);
    k_cls<<<1, 64>>>(Wc1, bc1, Wc2, bc2, out);
}